// round 1
// baseline (speedup 1.0000x reference)
#include <cuda_runtime.h>
#include <math.h>

#define B_SIZE 32768
#define E_DIM  256
#define NF     512
#define NWIN   6
#define BN_EPS 1e-5

// ---------------- scratch (static device arrays; no allocation) ----------------
__device__ float  g_out1[(size_t)2 * B_SIZE * NF];  // [w][b][f], w=0,1  (pre-BN, bias included)
__device__ float  g_H   [(size_t)B_SIZE * NF];      // H + conv2_b
__device__ float  g_p2  [(size_t)4 * B_SIZE * NF];  // [k][b][f] : kr_k·W2_3 + kv_k·W2_4
__device__ double g_sum [NWIN * NF];
__device__ double g_sq  [NWIN * NF];
__device__ float  g_scale[NWIN * NF];
__device__ float  g_shift[NWIN * NF];

// ---------------- kernel 0: zero stats ----------------
__global__ void zero_stats_kernel() {
    int i = blockIdx.x * blockDim.x + threadIdx.x;
    if (i < NWIN * NF) { g_sum[i] = 0.0; g_sq[i] = 0.0; }
}

// ---------------- kernel A: projections ----------------
// Per b: 11 embedding vectors: v0=fr0(roles), v1=fv0(val), v2=fv1(val),
//        v3..6=kr_k(roles), v7..10=kv_k(val)
// 7 weight slices: 0=W1[.,0,:] 1=W1[.,1,:] 2..6=W2[.,0..4,:]
#define MB 32
#define FT 64
#define EC 8

__global__ __launch_bounds__(256) void proj_kernel(
    const int*   __restrict__ x,
    const float* __restrict__ emb_r,
    const float* __restrict__ emb_v,
    const float* __restrict__ w1,
    const float* __restrict__ b1,
    const float* __restrict__ w2,
    const float* __restrict__ b2)
{
    __shared__ int   s_idx[MB][11];
    __shared__ float s_emb[11][MB][EC + 1];
    __shared__ float s_w  [7][FT][EC + 1];

    const int tid = threadIdx.x;
    const int fi  = tid & 15;   // f sub-index (strided mapping f = fi + 16*j)
    const int bi  = tid >> 4;   // b group (2 rows each)
    const int b0  = blockIdx.y * MB;
    const int f0  = blockIdx.x * FT;

    if (tid < MB) {
        const int* row = x + (size_t)(b0 + tid) * 12;
        s_idx[tid][0] = row[0];   // fr0
        s_idx[tid][1] = row[1];   // fv0
        s_idx[tid][2] = row[3];   // fv1
#pragma unroll
        for (int k = 0; k < 4; k++) {
            s_idx[tid][3 + k] = row[4 + 2 * k];  // kr_k
            s_idx[tid][7 + k] = row[5 + 2 * k];  // kv_k
        }
    }
    __syncthreads();

    float a10[2][4], a11[2][4], aH[2][4], a2[4][2][4];
#pragma unroll
    for (int i = 0; i < 2; i++)
#pragma unroll
        for (int j = 0; j < 4; j++) {
            a10[i][j] = 0.f; a11[i][j] = 0.f; aH[i][j] = 0.f;
            a2[0][i][j] = 0.f; a2[1][i][j] = 0.f; a2[2][i][j] = 0.f; a2[3][i][j] = 0.f;
        }

    for (int e0 = 0; e0 < E_DIM; e0 += EC) {
        // load embedding tile: 11*MB*EC = 2816 elements
#pragma unroll 1
        for (int t = tid; t < 11 * MB * EC; t += 256) {
            int e = t & (EC - 1);
            int b = (t >> 3) & (MB - 1);
            int v = t >> 8;  // / (MB*EC)
            const float* tab = (v == 0 || (v >= 3 && v < 7)) ? emb_r : emb_v;
            s_emb[v][b][e] = tab[(size_t)s_idx[b][v] * E_DIM + e0 + e];
        }
        // load weight tile: 7*FT*EC = 3584 elements
#pragma unroll 1
        for (int t = tid; t < 7 * FT * EC; t += 256) {
            int e = t & (EC - 1);
            int f = (t >> 3) & (FT - 1);
            int s = t >> 9;  // / (FT*EC)
            float val;
            if (s < 2) val = w1[((size_t)(f0 + f) * 2 + s) * E_DIM + e0 + e];
            else       val = w2[((size_t)(f0 + f) * 5 + (s - 2)) * E_DIM + e0 + e];
            s_w[s][f][e] = val;
        }
        __syncthreads();

#pragma unroll
        for (int e = 0; e < EC; e++) {
            float ev[2][11];
#pragma unroll
            for (int i = 0; i < 2; i++)
#pragma unroll
                for (int v = 0; v < 11; v++)
                    ev[i][v] = s_emb[v][bi * 2 + i][e];
#pragma unroll
            for (int j = 0; j < 4; j++) {
                const int fl = fi + 16 * j;
                float w10 = s_w[0][fl][e];
                float w11 = s_w[1][fl][e];
                float w20 = s_w[2][fl][e];
                float w21 = s_w[3][fl][e];
                float w22 = s_w[4][fl][e];
                float w23 = s_w[5][fl][e];
                float w24 = s_w[6][fl][e];
#pragma unroll
                for (int i = 0; i < 2; i++) {
                    a10[i][j] += ev[i][1] * w10 + ev[i][0] * w11;
                    a11[i][j] += ev[i][2] * w10 + ev[i][0] * w11;
                    aH [i][j] += ev[i][1] * w20 + ev[i][0] * w21 + ev[i][2] * w22;
                    a2[0][i][j] += ev[i][3] * w23 + ev[i][7]  * w24;
                    a2[1][i][j] += ev[i][4] * w23 + ev[i][8]  * w24;
                    a2[2][i][j] += ev[i][5] * w23 + ev[i][9]  * w24;
                    a2[3][i][j] += ev[i][6] * w23 + ev[i][10] * w24;
                }
            }
        }
        __syncthreads();
    }

    // epilogue
#pragma unroll
    for (int j = 0; j < 4; j++) {
        const int f = f0 + fi + 16 * j;
        const float bb1 = b1[f];
        const float bb2 = b2[f];
#pragma unroll
        for (int i = 0; i < 2; i++) {
            const int b = b0 + bi * 2 + i;
            g_out1[(size_t)b * NF + f]                        = a10[i][j] + bb1;
            g_out1[((size_t)B_SIZE + b) * NF + f]             = a11[i][j] + bb1;
            g_H   [(size_t)b * NF + f]                        = aH[i][j] + bb2;
            g_p2  [((size_t)0 * B_SIZE + b) * NF + f]         = a2[0][i][j];
            g_p2  [((size_t)1 * B_SIZE + b) * NF + f]         = a2[1][i][j];
            g_p2  [((size_t)2 * B_SIZE + b) * NF + f]         = a2[2][i][j];
            g_p2  [((size_t)3 * B_SIZE + b) * NF + f]         = a2[3][i][j];
        }
    }
}

// ---------------- kernel B: batch statistics ----------------
// grid (4 f-tiles of 128, 256 b-chunks of 128), block 128
__global__ __launch_bounds__(128) void stats_kernel() {
    const int f  = blockIdx.x * 128 + threadIdx.x;
    const int b0 = blockIdx.y * 128;
    double s[6] = {0, 0, 0, 0, 0, 0};
    double q[6] = {0, 0, 0, 0, 0, 0};
    for (int bb = 0; bb < 128; bb++) {
        const int b = b0 + bb;
        float o0 = g_out1[(size_t)b * NF + f];
        float o1 = g_out1[((size_t)B_SIZE + b) * NF + f];
        float h  = g_H[(size_t)b * NF + f];
        s[0] += o0; q[0] += (double)o0 * o0;
        s[1] += o1; q[1] += (double)o1 * o1;
#pragma unroll
        for (int k = 0; k < 4; k++) {
            float v = h + g_p2[((size_t)k * B_SIZE + b) * NF + f];
            s[2 + k] += v; q[2 + k] += (double)v * v;
        }
    }
#pragma unroll
    for (int w = 0; w < 6; w++) {
        atomicAdd(&g_sum[w * NF + f], s[w]);
        atomicAdd(&g_sq [w * NF + f], q[w]);
    }
}

// ---------------- kernel D: finalize scale/shift ----------------
__global__ void bn_finalize_kernel(
    const float* __restrict__ g1, const float* __restrict__ be1,
    const float* __restrict__ g2, const float* __restrict__ be2)
{
    int c = blockIdx.x * blockDim.x + threadIdx.x;
    if (c >= NWIN * NF) return;
    int w = c >> 9;
    int f = c & (NF - 1);
    double mean = g_sum[c] / (double)B_SIZE;
    double var  = g_sq[c] / (double)B_SIZE - mean * mean;
    float gamma = (w < 2) ? g1[f] : g2[f];
    float beta  = (w < 2) ? be1[f] : be2[f];
    double istd = rsqrt(var + BN_EPS);
    float sc = (float)(gamma * istd);
    g_scale[c] = sc;
    g_shift[c] = beta - (float)(mean * (double)sc);
}

// ---------------- kernel C: BN + relu + min + fc ----------------
__global__ __launch_bounds__(128) void final_kernel(
    const float* __restrict__ fc_w,
    const float* __restrict__ fc_b,
    float* __restrict__ out)
{
    const int b   = blockIdx.x;
    const int tid = threadIdx.x;
    const int f   = tid * 4;

    float4 o0 = *(const float4*)&g_out1[(size_t)b * NF + f];
    float4 o1 = *(const float4*)&g_out1[((size_t)B_SIZE + b) * NF + f];
    float4 h  = *(const float4*)&g_H[(size_t)b * NF + f];
    float4 p[4];
#pragma unroll
    for (int k = 0; k < 4; k++)
        p[k] = *(const float4*)&g_p2[((size_t)k * B_SIZE + b) * NF + f];

    float acc = 0.f;
#pragma unroll
    for (int l = 0; l < 4; l++) {
        const int fl = f + l;
        float x0 = (l == 0 ? o0.x : l == 1 ? o0.y : l == 2 ? o0.z : o0.w);
        float x1 = (l == 0 ? o1.x : l == 1 ? o1.y : l == 2 ? o1.z : o1.w);
        float hh = (l == 0 ? h.x  : l == 1 ? h.y  : l == 2 ? h.z  : h.w);
        float m = fmaxf(0.f, x0 * g_scale[0 * NF + fl] + g_shift[0 * NF + fl]);
        m = fminf(m, fmaxf(0.f, x1 * g_scale[1 * NF + fl] + g_shift[1 * NF + fl]));
#pragma unroll
        for (int k = 0; k < 4; k++) {
            float pk = (l == 0 ? p[k].x : l == 1 ? p[k].y : l == 2 ? p[k].z : p[k].w);
            float v = hh + pk;
            m = fminf(m, fmaxf(0.f, v * g_scale[(2 + k) * NF + fl] + g_shift[(2 + k) * NF + fl]));
        }
        acc += fc_w[fl] * m;
    }

    // block reduce (128 threads = 4 warps)
    __shared__ float red[4];
#pragma unroll
    for (int o = 16; o > 0; o >>= 1) acc += __shfl_down_sync(0xFFFFFFFFu, acc, o);
    if ((tid & 31) == 0) red[tid >> 5] = acc;
    __syncthreads();
    if (tid == 0) out[b] = red[0] + red[1] + red[2] + red[3] + fc_b[0];
}

// ---------------- launch ----------------
extern "C" void kernel_launch(void* const* d_in, const int* in_sizes, int n_in,
                              void* d_out, int out_size) {
    // inputs: x_batch, [arity], emb_roles, emb_values, conv1_w, conv1_b,
    //         bn1_gamma, bn1_beta, conv2_w, conv2_b, bn2_gamma, bn2_beta, fc_w, fc_b
    int o = (in_sizes[1] == 1) ? 1 : 0;  // skip scalar arity if present
    const int*   x      = (const int*)  d_in[0];
    const float* emb_r  = (const float*)d_in[1 + o];
    const float* emb_v  = (const float*)d_in[2 + o];
    const float* w1     = (const float*)d_in[3 + o];
    const float* b1     = (const float*)d_in[4 + o];
    const float* bn1_g  = (const float*)d_in[5 + o];
    const float* bn1_b  = (const float*)d_in[6 + o];
    const float* w2     = (const float*)d_in[7 + o];
    const float* b2     = (const float*)d_in[8 + o];
    const float* bn2_g  = (const float*)d_in[9 + o];
    const float* bn2_b  = (const float*)d_in[10 + o];
    const float* fc_w   = (const float*)d_in[11 + o];
    const float* fc_b   = (const float*)d_in[12 + o];
    float* out = (float*)d_out;

    zero_stats_kernel<<<(NWIN * NF + 255) / 256, 256>>>();

    dim3 gA(NF / FT, B_SIZE / MB);  // (8, 1024)
    proj_kernel<<<gA, 256>>>(x, emb_r, emb_v, w1, b1, w2, b2);

    stats_kernel<<<dim3(NF / 128, B_SIZE / 128), 128>>>();

    bn_finalize_kernel<<<(NWIN * NF + 255) / 256, 256>>>(bn1_g, bn1_b, bn2_g, bn2_b);

    final_kernel<<<B_SIZE, 128>>>(fc_w, fc_b, out);
}

// round 6
// speedup vs baseline: 4.3977x; 4.3977x over previous
#include <cuda_runtime.h>
#include <cuda_bf16.h>
#include <math.h>
#include <stdint.h>

#define B_SIZE 32768
#define E_DIM  256
#define NF     512
#define NWIN   6
#define BN_EPS 1e-5
#define KCAT   1792   // 512 (type1) + 512 (type2) + 768 (typeH)
#define NRV    50000

// ---------------- scratch (static device arrays) ----------------
__device__ float  g_out1[(size_t)2 * B_SIZE * NF];
__device__ float  g_H   [(size_t)B_SIZE * NF];
__device__ float  g_p2  [(size_t)4 * B_SIZE * NF];
__device__ double g_sum [NWIN * NF];
__device__ double g_sq  [NWIN * NF];
__device__ float  g_scale[NWIN * NF];
__device__ float  g_shift[NWIN * NF];

// bf16 split tables / weights
__device__ __nv_bfloat16 g_er_hi[(size_t)NRV * E_DIM];
__device__ __nv_bfloat16 g_er_lo[(size_t)NRV * E_DIM];
__device__ __nv_bfloat16 g_ev_hi[(size_t)NRV * E_DIM];
__device__ __nv_bfloat16 g_ev_lo[(size_t)NRV * E_DIM];
__device__ __nv_bfloat16 g_w_hi[(size_t)NF * KCAT];
__device__ __nv_bfloat16 g_w_lo[(size_t)NF * KCAT];

// ---------------- helpers ----------------
__device__ __forceinline__ uint32_t smem_u32(const void* p) {
    uint32_t a;
    asm("{ .reg .u64 t; cvta.to.shared.u64 t, %1; cvt.u32.u64 %0, t; }" : "=r"(a) : "l"(p));
    return a;
}
__device__ __forceinline__ void cp16(uint32_t dst, const void* src) {
    asm volatile("cp.async.cg.shared.global [%0], [%1], 16;" :: "r"(dst), "l"(src));
}
__device__ __forceinline__ void ldsm4(uint32_t& r0, uint32_t& r1, uint32_t& r2, uint32_t& r3,
                                      uint32_t addr) {
    asm volatile("ldmatrix.sync.aligned.m8n8.x4.shared.b16 {%0,%1,%2,%3}, [%4];"
                 : "=r"(r0), "=r"(r1), "=r"(r2), "=r"(r3) : "r"(addr));
}
__device__ __forceinline__ void mma16816(float* d, const uint32_t* a, uint32_t b0, uint32_t b1) {
    asm volatile(
        "mma.sync.aligned.m16n8k16.row.col.f32.bf16.bf16.f32 "
        "{%0,%1,%2,%3}, {%4,%5,%6,%7}, {%8,%9}, {%0,%1,%2,%3};"
        : "+f"(d[0]), "+f"(d[1]), "+f"(d[2]), "+f"(d[3])
        : "r"(a[0]), "r"(a[1]), "r"(a[2]), "r"(a[3]), "r"(b0), "r"(b1));
}

// ---------------- prep kernels ----------------
__global__ void prep_tables_kernel(const float* __restrict__ er,
                                   const float* __restrict__ ev,
                                   int nre, int nve) {
    int total = nre + nve;
    for (int i = blockIdx.x * blockDim.x + threadIdx.x; i < total; i += gridDim.x * blockDim.x) {
        if (i < nre) {
            float x = er[i];
            __nv_bfloat16 hi = __float2bfloat16_rn(x);
            g_er_hi[i] = hi;
            g_er_lo[i] = __float2bfloat16_rn(x - __bfloat162float(hi));
        } else {
            int j = i - nre;
            float x = ev[j];
            __nv_bfloat16 hi = __float2bfloat16_rn(x);
            g_ev_hi[j] = hi;
            g_ev_lo[j] = __float2bfloat16_rn(x - __bfloat162float(hi));
        }
    }
}

__global__ void prep_w_kernel(const float* __restrict__ w1, const float* __restrict__ w2) {
    for (int i = blockIdx.x * blockDim.x + threadIdx.x; i < NF * KCAT; i += gridDim.x * blockDim.x) {
        int f = i / KCAT, k = i % KCAT;
        float v;
        if      (k < 256)  v = w1[((size_t)f * 2 + 0) * E_DIM + k];
        else if (k < 512)  v = w1[((size_t)f * 2 + 1) * E_DIM + (k - 256)];
        else if (k < 768)  v = w2[((size_t)f * 5 + 3) * E_DIM + (k - 512)];
        else if (k < 1024) v = w2[((size_t)f * 5 + 4) * E_DIM + (k - 768)];
        else if (k < 1280) v = w2[((size_t)f * 5 + 0) * E_DIM + (k - 1024)];
        else if (k < 1536) v = w2[((size_t)f * 5 + 1) * E_DIM + (k - 1280)];
        else               v = w2[((size_t)f * 5 + 2) * E_DIM + (k - 1536)];
        __nv_bfloat16 hi = __float2bfloat16_rn(v);
        g_w_hi[i] = hi;
        g_w_lo[i] = __float2bfloat16_rn(v - __bfloat162float(hi));
    }
}

__global__ void zero_stats_kernel() {
    int i = blockIdx.x * blockDim.x + threadIdx.x;
    if (i < NWIN * NF) { g_sum[i] = 0.0; g_sq[i] = 0.0; }
}

// ---------------- GEMM kernel (mma.sync bf16x3 split) ----------------
// grid: (1792 M-tiles, 4 N-tiles of 128), block 256 (8 warps, 4x2; warp tile 32x64)
// tiles 0..511: type0 (out1, j=tile>>8); 512..1535: type1 (p2, k=(tile-512)>>8); 1536..1791: typeH
// smem: [0,512) bias; [1024, 1024+2*65536) double-buffered tiles.
// per buffer: AHI 16K | ALO 16K | BHI 16K | BLO 16K  (128 rows x 128B, SW128)
#define SMEM_TOTAL (1024 + 2 * 65536)

__global__ __launch_bounds__(256, 1) void gemm_kernel(
    const int* __restrict__ x,
    const float* __restrict__ b1,
    const float* __restrict__ b2)
{
    extern __shared__ char smem[];
    const uint32_t sb = smem_u32(smem);
    const int tid = threadIdx.x, wid = tid >> 5, lane = tid & 31;
    const int tile = blockIdx.x;
    const int f0 = blockIdx.y * 128;

    int type, sub, b0, nch, kbase;
    if (tile < 512)       { type = 0; sub = tile >> 8;         b0 = (tile & 255) * 128;         nch = 8;  kbase = 0; }
    else if (tile < 1536) { type = 1; sub = (tile - 512) >> 8; b0 = ((tile - 512) & 255) * 128; nch = 8;  kbase = 512; }
    else                  { type = 2; sub = 0;                 b0 = (tile - 1536) * 128;        nch = 12; kbase = 1024; }

    // bias into smem
    {
        const float* bp = (type == 0) ? b1 : ((type == 2) ? b2 : (const float*)0);
        float* sbias = (float*)smem;
        if (tid < 128) sbias[tid] = bp ? bp[f0 + tid] : 0.0f;
    }

    // ---- chunk loader (cp.async gather) ----
    const int row = tid >> 1, half = tid & 1;
    auto issue_loads = [&](int cc) {
        const uint32_t tb = sb + 1024 + (uint32_t)(cc & 1) * 65536;
        // A row gather
        {
            const int cq = cc >> 2, e0 = (cc & 3) * 64;
            int col; const __nv_bfloat16 *th, *tl;
            if (type == 0) {
                if (cq == 0) { col = 2 * sub + 1; th = g_ev_hi; tl = g_ev_lo; }
                else         { col = 0;           th = g_er_hi; tl = g_er_lo; }
            } else if (type == 1) {
                if (cq == 0) { col = 4 + 2 * sub; th = g_er_hi; tl = g_er_lo; }
                else         { col = 5 + 2 * sub; th = g_ev_hi; tl = g_ev_lo; }
            } else {
                if (cq == 0)      { col = 1; th = g_ev_hi; tl = g_ev_lo; }
                else if (cq == 1) { col = 0; th = g_er_hi; tl = g_er_lo; }
                else              { col = 3; th = g_ev_hi; tl = g_ev_lo; }
            }
            const int idx = __ldg(x + (size_t)(b0 + row) * 12 + col);
            const char* sh = (const char*)(th + (size_t)idx * E_DIM + e0);
            const char* sl = (const char*)(tl + (size_t)idx * E_DIM + e0);
            const uint32_t ro = (uint32_t)row * 128;
            const uint32_t xr = (uint32_t)(row & 7);
#pragma unroll
            for (int g = 0; g < 4; g++) {
                const int gg = half * 4 + g;
                const uint32_t so = ro + (uint32_t)((gg ^ xr) * 16);
                cp16(tb + so,         sh + gg * 16);
                cp16(tb + 16384 + so, sl + gg * 16);
            }
        }
        // B rows (feature f0+row)
        {
            const char* ph = (const char*)(g_w_hi + (size_t)(f0 + row) * KCAT + kbase + cc * 64);
            const char* pl = (const char*)(g_w_lo + (size_t)(f0 + row) * KCAT + kbase + cc * 64);
            const uint32_t ro = (uint32_t)row * 128;
            const uint32_t xr = (uint32_t)(row & 7);
#pragma unroll
            for (int g = 0; g < 4; g++) {
                const int gg = half * 4 + g;
                const uint32_t so = ro + (uint32_t)((gg ^ xr) * 16);
                cp16(tb + 32768 + so, ph + gg * 16);
                cp16(tb + 49152 + so, pl + gg * 16);
            }
        }
        asm volatile("cp.async.commit_group;" ::: "memory");
    };

    // ---- per-warp frag addressing ----
    const int warpM = (wid & 3) * 32;
    const int warpN = (wid >> 2) * 64;
    uint32_t aOff[2], aXor[2];
#pragma unroll
    for (int mi = 0; mi < 2; mi++) {
        const int r = warpM + mi * 16 + (lane & 15);
        aOff[mi] = (uint32_t)r * 128;
        aXor[mi] = (uint32_t)(r & 7);
    }
    const uint32_t aSel = (uint32_t)((lane >> 4) & 1);
    uint32_t bOff[4], bXor[4];
#pragma unroll
    for (int p = 0; p < 4; p++) {
        const int r = warpN + p * 16 + (lane & 7) + (((lane >> 4) & 1) << 3);
        bOff[p] = (uint32_t)r * 128;
        bXor[p] = (uint32_t)(r & 7);
    }
    const uint32_t bSel = (uint32_t)((lane >> 3) & 1);

    float acc[2][8][4];
#pragma unroll
    for (int mi = 0; mi < 2; mi++)
#pragma unroll
        for (int ni = 0; ni < 8; ni++)
#pragma unroll
            for (int q = 0; q < 4; q++) acc[mi][ni][q] = 0.f;

    issue_loads(0);

    for (int c = 0; c < nch; c++) {
        if (c + 1 < nch) issue_loads(c + 1);
        if (c + 1 < nch) asm volatile("cp.async.wait_group 1;" ::: "memory");
        else             asm volatile("cp.async.wait_group 0;" ::: "memory");
        __syncthreads();

        const uint32_t tb = sb + 1024 + (uint32_t)(c & 1) * 65536;
#pragma unroll
        for (int s = 0; s < 4; s++) {
            uint32_t ah[2][4], al[2][4];
#pragma unroll
            for (int mi = 0; mi < 2; mi++) {
                const uint32_t blk = (uint32_t)(2 * s) + aSel;
                const uint32_t ad = tb + aOff[mi] + ((blk ^ aXor[mi]) * 16);
                ldsm4(ah[mi][0], ah[mi][1], ah[mi][2], ah[mi][3], ad);
                ldsm4(al[mi][0], al[mi][1], al[mi][2], al[mi][3], ad + 16384);
            }
            uint32_t bh[4][4], bl[4][4];
#pragma unroll
            for (int p = 0; p < 4; p++) {
                const uint32_t blk = (uint32_t)(2 * s) + bSel;
                const uint32_t bd = tb + 32768 + bOff[p] + ((blk ^ bXor[p]) * 16);
                ldsm4(bh[p][0], bh[p][1], bh[p][2], bh[p][3], bd);
                ldsm4(bl[p][0], bl[p][1], bl[p][2], bl[p][3], bd + 16384);
            }
#pragma unroll
            for (int mi = 0; mi < 2; mi++)
#pragma unroll
                for (int ni = 0; ni < 8; ni++) {
                    const int p = ni >> 1, o = (ni & 1) * 2;
                    mma16816(acc[mi][ni], ah[mi], bh[p][o], bh[p][o + 1]);
                    mma16816(acc[mi][ni], ah[mi], bl[p][o], bl[p][o + 1]);
                    mma16816(acc[mi][ni], al[mi], bh[p][o], bh[p][o + 1]);
                }
        }
        __syncthreads();
    }

    // ---- epilogue ----
    float* plane; size_t rowbase;
    if (type == 0)      { plane = g_out1; rowbase = (size_t)sub * B_SIZE + b0; }
    else if (type == 1) { plane = g_p2;   rowbase = (size_t)sub * B_SIZE + b0; }
    else                { plane = g_H;    rowbase = (size_t)b0; }

    const float* sbias = (const float*)smem;
    const int lr = lane >> 2, lc = (lane & 3) * 2;
#pragma unroll
    for (int mi = 0; mi < 2; mi++) {
        const size_t r0 = rowbase + warpM + mi * 16 + lr;
#pragma unroll
        for (int ni = 0; ni < 8; ni++) {
            const int colLocal = warpN + ni * 8 + lc;
            const int f = f0 + colLocal;
            const float bi0 = sbias[colLocal], bi1 = sbias[colLocal + 1];
            float2 v0 = {acc[mi][ni][0] + bi0, acc[mi][ni][1] + bi1};
            float2 v1 = {acc[mi][ni][2] + bi0, acc[mi][ni][3] + bi1};
            *(float2*)(plane + r0 * NF + f)       = v0;
            *(float2*)(plane + (r0 + 8) * NF + f) = v1;
        }
    }
}

// ---------------- stats / finalize / final ----------------
__global__ __launch_bounds__(128) void stats_kernel() {
    const int f  = blockIdx.x * 128 + threadIdx.x;
    const int b0 = blockIdx.y * 128;
    double s[6] = {0, 0, 0, 0, 0, 0};
    double q[6] = {0, 0, 0, 0, 0, 0};
    for (int bb = 0; bb < 128; bb++) {
        const int b = b0 + bb;
        float o0 = g_out1[(size_t)b * NF + f];
        float o1 = g_out1[((size_t)B_SIZE + b) * NF + f];
        float h  = g_H[(size_t)b * NF + f];
        s[0] += o0; q[0] += (double)o0 * o0;
        s[1] += o1; q[1] += (double)o1 * o1;
#pragma unroll
        for (int k = 0; k < 4; k++) {
            float v = h + g_p2[((size_t)k * B_SIZE + b) * NF + f];
            s[2 + k] += v; q[2 + k] += (double)v * v;
        }
    }
#pragma unroll
    for (int w = 0; w < 6; w++) {
        atomicAdd(&g_sum[w * NF + f], s[w]);
        atomicAdd(&g_sq [w * NF + f], q[w]);
    }
}

__global__ void bn_finalize_kernel(
    const float* __restrict__ g1, const float* __restrict__ be1,
    const float* __restrict__ g2, const float* __restrict__ be2)
{
    int c = blockIdx.x * blockDim.x + threadIdx.x;
    if (c >= NWIN * NF) return;
    int w = c >> 9;
    int f = c & (NF - 1);
    double mean = g_sum[c] / (double)B_SIZE;
    double var  = g_sq[c] / (double)B_SIZE - mean * mean;
    float gamma = (w < 2) ? g1[f] : g2[f];
    float beta  = (w < 2) ? be1[f] : be2[f];
    double istd = rsqrt(var + BN_EPS);
    float sc = (float)(gamma * istd);
    g_scale[c] = sc;
    g_shift[c] = beta - (float)(mean * (double)sc);
}

__global__ __launch_bounds__(128) void final_kernel(
    const float* __restrict__ fc_w,
    const float* __restrict__ fc_b,
    float* __restrict__ out)
{
    const int b   = blockIdx.x;
    const int tid = threadIdx.x;
    const int f   = tid * 4;

    float4 o0 = *(const float4*)&g_out1[(size_t)b * NF + f];
    float4 o1 = *(const float4*)&g_out1[((size_t)B_SIZE + b) * NF + f];
    float4 h  = *(const float4*)&g_H[(size_t)b * NF + f];
    float4 p[4];
#pragma unroll
    for (int k = 0; k < 4; k++)
        p[k] = *(const float4*)&g_p2[((size_t)k * B_SIZE + b) * NF + f];

    float acc = 0.f;
#pragma unroll
    for (int l = 0; l < 4; l++) {
        const int fl = f + l;
        float x0 = (l == 0 ? o0.x : l == 1 ? o0.y : l == 2 ? o0.z : o0.w);
        float x1 = (l == 0 ? o1.x : l == 1 ? o1.y : l == 2 ? o1.z : o1.w);
        float hh = (l == 0 ? h.x  : l == 1 ? h.y  : l == 2 ? h.z  : h.w);
        float m = fmaxf(0.f, x0 * g_scale[0 * NF + fl] + g_shift[0 * NF + fl]);
        m = fminf(m, fmaxf(0.f, x1 * g_scale[1 * NF + fl] + g_shift[1 * NF + fl]));
#pragma unroll
        for (int k = 0; k < 4; k++) {
            float pk = (l == 0 ? p[k].x : l == 1 ? p[k].y : l == 2 ? p[k].z : p[k].w);
            float v = hh + pk;
            m = fminf(m, fmaxf(0.f, v * g_scale[(2 + k) * NF + fl] + g_shift[(2 + k) * NF + fl]));
        }
        acc += fc_w[fl] * m;
    }

    __shared__ float red[4];
#pragma unroll
    for (int o = 16; o > 0; o >>= 1) acc += __shfl_down_sync(0xFFFFFFFFu, acc, o);
    if ((tid & 31) == 0) red[tid >> 5] = acc;
    __syncthreads();
    if (tid == 0) out[b] = red[0] + red[1] + red[2] + red[3] + fc_b[0];
}

// ---------------- launch ----------------
extern "C" void kernel_launch(void* const* d_in, const int* in_sizes, int n_in,
                              void* d_out, int out_size) {
    int o = (in_sizes[1] == 1) ? 1 : 0;  // skip scalar arity if present
    const int*   x      = (const int*)  d_in[0];
    const float* emb_r  = (const float*)d_in[1 + o];
    const float* emb_v  = (const float*)d_in[2 + o];
    const float* w1     = (const float*)d_in[3 + o];
    const float* b1     = (const float*)d_in[4 + o];
    const float* bn1_g  = (const float*)d_in[5 + o];
    const float* bn1_b  = (const float*)d_in[6 + o];
    const float* w2     = (const float*)d_in[7 + o];
    const float* b2     = (const float*)d_in[8 + o];
    const float* bn2_g  = (const float*)d_in[9 + o];
    const float* bn2_b  = (const float*)d_in[10 + o];
    const float* fc_w   = (const float*)d_in[11 + o];
    const float* fc_b   = (const float*)d_in[12 + o];
    float* out = (float*)d_out;

    cudaFuncSetAttribute(gemm_kernel, cudaFuncAttributeMaxDynamicSharedMemorySize, SMEM_TOTAL);

    const int nre = in_sizes[1 + o];  // NR*E
    const int nve = in_sizes[2 + o];  // NV*E

    prep_tables_kernel<<<2048, 256>>>(emb_r, emb_v, nre, nve);
    prep_w_kernel<<<1024, 256>>>(w1, w2);
    zero_stats_kernel<<<(NWIN * NF + 255) / 256, 256>>>();

    gemm_kernel<<<dim3(1792, 4), 256, SMEM_TOTAL>>>(x, b1, b2);

    stats_kernel<<<dim3(NF / 128, B_SIZE / 128), 128>>>();
    bn_finalize_kernel<<<(NWIN * NF + 255) / 256, 256>>>(bn1_g, bn1_b, bn2_g, bn2_b);
    final_kernel<<<B_SIZE, 128>>>(fc_w, fc_b, out);
}

// round 8
// speedup vs baseline: 5.2134x; 1.1855x over previous
#include <cuda_runtime.h>
#include <cuda_fp16.h>
#include <math.h>
#include <stdint.h>

#define B_SIZE 32768
#define E_DIM  256
#define NF     512
#define NWIN   6
#define BN_EPS 1e-5
#define KCAT   1792   // 512 (type0) + 512 (type1) + 768 (typeH)
#define NRV    50000
#define ASCALE 256.0f
#define DSCALE (1.0f / 256.0f)

// ---------------- scratch (static device arrays) ----------------
__device__ float  g_out1[(size_t)2 * B_SIZE * NF];
__device__ float  g_H   [(size_t)B_SIZE * NF];
__device__ float  g_p2  [(size_t)4 * B_SIZE * NF];
__device__ double g_sum [NWIN * NF];
__device__ double g_sq  [NWIN * NF];
__device__ float  g_scale[NWIN * NF];
__device__ float  g_shift[NWIN * NF];

// fp16 split tables (scaled x256) / fp16 weights (unscaled)
__device__ __half g_er_hi[(size_t)NRV * E_DIM];
__device__ __half g_er_lo[(size_t)NRV * E_DIM];
__device__ __half g_ev_hi[(size_t)NRV * E_DIM];
__device__ __half g_ev_lo[(size_t)NRV * E_DIM];
__device__ __half g_w_h [(size_t)NF * KCAT];

// ---------------- helpers ----------------
__device__ __forceinline__ uint32_t smem_u32(const void* p) {
    uint32_t a;
    asm("{ .reg .u64 t; cvta.to.shared.u64 t, %1; cvt.u32.u64 %0, t; }" : "=r"(a) : "l"(p));
    return a;
}
__device__ __forceinline__ void cp16(uint32_t dst, const void* src) {
    asm volatile("cp.async.cg.shared.global [%0], [%1], 16;" :: "r"(dst), "l"(src));
}
__device__ __forceinline__ void ldsm4(uint32_t& r0, uint32_t& r1, uint32_t& r2, uint32_t& r3,
                                      uint32_t addr) {
    asm volatile("ldmatrix.sync.aligned.m8n8.x4.shared.b16 {%0,%1,%2,%3}, [%4];"
                 : "=r"(r0), "=r"(r1), "=r"(r2), "=r"(r3) : "r"(addr));
}
__device__ __forceinline__ void mma16816(float* d, const uint32_t* a, uint32_t b0, uint32_t b1) {
    asm volatile(
        "mma.sync.aligned.m16n8k16.row.col.f32.f16.f16.f32 "
        "{%0,%1,%2,%3}, {%4,%5,%6,%7}, {%8,%9}, {%0,%1,%2,%3};"
        : "+f"(d[0]), "+f"(d[1]), "+f"(d[2]), "+f"(d[3])
        : "r"(a[0]), "r"(a[1]), "r"(a[2]), "r"(a[3]), "r"(b0), "r"(b1));
}

// ---------------- prep kernels ----------------
__global__ void prep_tables_kernel(const float* __restrict__ er,
                                   const float* __restrict__ ev,
                                   int nre, int nve) {
    int total = nre + nve;
    for (int i = blockIdx.x * blockDim.x + threadIdx.x; i < total; i += gridDim.x * blockDim.x) {
        if (i < nre) {
            float x = er[i] * ASCALE;
            __half hi = __float2half_rn(x);
            g_er_hi[i] = hi;
            g_er_lo[i] = __float2half_rn(x - __half2float(hi));
        } else {
            int j = i - nre;
            float x = ev[j] * ASCALE;
            __half hi = __float2half_rn(x);
            g_ev_hi[j] = hi;
            g_ev_lo[j] = __float2half_rn(x - __half2float(hi));
        }
    }
}

__global__ void prep_w_kernel(const float* __restrict__ w1, const float* __restrict__ w2) {
    for (int i = blockIdx.x * blockDim.x + threadIdx.x; i < NF * KCAT; i += gridDim.x * blockDim.x) {
        int f = i / KCAT, k = i % KCAT;
        float v;
        if      (k < 256)  v = w1[((size_t)f * 2 + 0) * E_DIM + k];
        else if (k < 512)  v = w1[((size_t)f * 2 + 1) * E_DIM + (k - 256)];
        else if (k < 768)  v = w2[((size_t)f * 5 + 3) * E_DIM + (k - 512)];
        else if (k < 1024) v = w2[((size_t)f * 5 + 4) * E_DIM + (k - 768)];
        else if (k < 1280) v = w2[((size_t)f * 5 + 0) * E_DIM + (k - 1024)];
        else if (k < 1536) v = w2[((size_t)f * 5 + 1) * E_DIM + (k - 1280)];
        else               v = w2[((size_t)f * 5 + 2) * E_DIM + (k - 1536)];
        g_w_h[i] = __float2half_rn(v);
    }
}

__global__ void zero_stats_kernel() {
    int i = blockIdx.x * blockDim.x + threadIdx.x;
    if (i < NWIN * NF) { g_sum[i] = 0.0; g_sq[i] = 0.0; }
}

// ---------------- GEMM kernel (mma.sync fp16, A-split 2-MMA) ----------------
// grid: (1792 M-tiles, 4 N-tiles of 128), block 256 (8 warps, 4x2; warp tile 32x64)
// smem: [0,512) bias; 3 stages of 48KB at 1024: per stage AHI 16K | ALO 16K | BH 16K
#define STAGE_BYTES 49152
#define SMEM_TOTAL  (1024 + 3 * STAGE_BYTES)

__global__ __launch_bounds__(256, 1) void gemm_kernel(
    const int* __restrict__ x,
    const float* __restrict__ b1,
    const float* __restrict__ b2)
{
    extern __shared__ char smem[];
    const uint32_t sb = smem_u32(smem);
    const int tid = threadIdx.x, wid = tid >> 5, lane = tid & 31;
    const int tile = blockIdx.x;
    const int f0 = blockIdx.y * 128;

    int type, sub, b0, nch, kbase;
    if (tile < 512)       { type = 0; sub = tile >> 8;         b0 = (tile & 255) * 128;         nch = 8;  kbase = 0; }
    else if (tile < 1536) { type = 1; sub = (tile - 512) >> 8; b0 = ((tile - 512) & 255) * 128; nch = 8;  kbase = 512; }
    else                  { type = 2; sub = 0;                 b0 = (tile - 1536) * 128;        nch = 12; kbase = 1024; }

    {
        const float* bp = (type == 0) ? b1 : ((type == 2) ? b2 : (const float*)0);
        float* sbias = (float*)smem;
        if (tid < 128) sbias[tid] = bp ? bp[f0 + tid] : 0.0f;
    }

    // ---- chunk loader (cp.async gather) ----
    const int row = tid >> 1, half = tid & 1;
    auto issue_loads = [&](int cc) {
        const uint32_t tb = sb + 1024 + (uint32_t)(cc % 3) * STAGE_BYTES;
        // A row gather (hi+lo)
        {
            const int cq = cc >> 2, e0 = (cc & 3) * 64;
            int col; const __half *th, *tl;
            if (type == 0) {
                if (cq == 0) { col = 2 * sub + 1; th = g_ev_hi; tl = g_ev_lo; }
                else         { col = 0;           th = g_er_hi; tl = g_er_lo; }
            } else if (type == 1) {
                if (cq == 0) { col = 4 + 2 * sub; th = g_er_hi; tl = g_er_lo; }
                else         { col = 5 + 2 * sub; th = g_ev_hi; tl = g_ev_lo; }
            } else {
                if (cq == 0)      { col = 1; th = g_ev_hi; tl = g_ev_lo; }
                else if (cq == 1) { col = 0; th = g_er_hi; tl = g_er_lo; }
                else              { col = 3; th = g_ev_hi; tl = g_ev_lo; }
            }
            const int idx = __ldg(x + (size_t)(b0 + row) * 12 + col);
            const char* sh = (const char*)(th + (size_t)idx * E_DIM + e0);
            const char* sl = (const char*)(tl + (size_t)idx * E_DIM + e0);
            const uint32_t ro = (uint32_t)row * 128;
            const uint32_t xr = (uint32_t)(row & 7);
#pragma unroll
            for (int g = 0; g < 4; g++) {
                const int gg = half * 4 + g;
                const uint32_t so = ro + (uint32_t)((gg ^ xr) * 16);
                cp16(tb + so,         sh + gg * 16);
                cp16(tb + 16384 + so, sl + gg * 16);
            }
        }
        // B rows (feature f0+row), hi only
        {
            const char* ph = (const char*)(g_w_h + (size_t)(f0 + row) * KCAT + kbase + cc * 64);
            const uint32_t ro = (uint32_t)row * 128;
            const uint32_t xr = (uint32_t)(row & 7);
#pragma unroll
            for (int g = 0; g < 4; g++) {
                const int gg = half * 4 + g;
                const uint32_t so = ro + (uint32_t)((gg ^ xr) * 16);
                cp16(tb + 32768 + so, ph + gg * 16);
            }
        }
        asm volatile("cp.async.commit_group;" ::: "memory");
    };

    // ---- per-warp frag addressing ----
    const int warpM = (wid & 3) * 32;
    const int warpN = (wid >> 2) * 64;
    uint32_t aOff[2], aXor[2];
#pragma unroll
    for (int mi = 0; mi < 2; mi++) {
        const int r = warpM + mi * 16 + (lane & 15);
        aOff[mi] = (uint32_t)r * 128;
        aXor[mi] = (uint32_t)(r & 7);
    }
    const uint32_t aSel = (uint32_t)((lane >> 4) & 1);
    uint32_t bOff[4], bXor[4];
#pragma unroll
    for (int p = 0; p < 4; p++) {
        const int r = warpN + p * 16 + (lane & 7) + (((lane >> 4) & 1) << 3);
        bOff[p] = (uint32_t)r * 128;
        bXor[p] = (uint32_t)(r & 7);
    }
    const uint32_t bSel = (uint32_t)((lane >> 3) & 1);

    float acc[2][8][4];
#pragma unroll
    for (int mi = 0; mi < 2; mi++)
#pragma unroll
        for (int ni = 0; ni < 8; ni++)
#pragma unroll
            for (int q = 0; q < 4; q++) acc[mi][ni][q] = 0.f;

    // frag double buffers
    uint32_t fah[2][2][4], fal[2][2][4], fb[2][4][4];

    issue_loads(0);
    if (nch > 1) issue_loads(1);

    for (int c = 0; c < nch; c++) {
        if (c + 2 < nch) issue_loads(c + 2);
        // wait until stage c is complete
        if (c + 2 < nch)      asm volatile("cp.async.wait_group 2;" ::: "memory");
        else if (c + 1 < nch) asm volatile("cp.async.wait_group 1;" ::: "memory");
        else                  asm volatile("cp.async.wait_group 0;" ::: "memory");
        __syncthreads();

        const uint32_t tb = sb + 1024 + (uint32_t)(c % 3) * STAGE_BYTES;

        // prefetch frags for s=0
        {
#pragma unroll
            for (int mi = 0; mi < 2; mi++) {
                const uint32_t ad = tb + aOff[mi] + ((aSel ^ aXor[mi]) * 16);
                ldsm4(fah[0][mi][0], fah[0][mi][1], fah[0][mi][2], fah[0][mi][3], ad);
                ldsm4(fal[0][mi][0], fal[0][mi][1], fal[0][mi][2], fal[0][mi][3], ad + 16384);
            }
#pragma unroll
            for (int p = 0; p < 4; p++) {
                const uint32_t bd = tb + 32768 + bOff[p] + ((bSel ^ bXor[p]) * 16);
                ldsm4(fb[0][p][0], fb[0][p][1], fb[0][p][2], fb[0][p][3], bd);
            }
        }

#pragma unroll
        for (int s = 0; s < 4; s++) {
            const int cur = s & 1;
            if (s < 3) {
                const int nxt = cur ^ 1;
                const uint32_t blk = (uint32_t)(2 * (s + 1));
#pragma unroll
                for (int mi = 0; mi < 2; mi++) {
                    const uint32_t ad = tb + aOff[mi] + (((blk + aSel) ^ aXor[mi]) * 16);
                    ldsm4(fah[nxt][mi][0], fah[nxt][mi][1], fah[nxt][mi][2], fah[nxt][mi][3], ad);
                    ldsm4(fal[nxt][mi][0], fal[nxt][mi][1], fal[nxt][mi][2], fal[nxt][mi][3], ad + 16384);
                }
#pragma unroll
                for (int p = 0; p < 4; p++) {
                    const uint32_t bd = tb + 32768 + bOff[p] + (((blk + bSel) ^ bXor[p]) * 16);
                    ldsm4(fb[nxt][p][0], fb[nxt][p][1], fb[nxt][p][2], fb[nxt][p][3], bd);
                }
            }
#pragma unroll
            for (int mi = 0; mi < 2; mi++)
#pragma unroll
                for (int ni = 0; ni < 8; ni++) {
                    const int p = ni >> 1, o = (ni & 1) * 2;
                    mma16816(acc[mi][ni], fah[cur][mi], fb[cur][p][o], fb[cur][p][o + 1]);
                    mma16816(acc[mi][ni], fal[cur][mi], fb[cur][p][o], fb[cur][p][o + 1]);
                }
        }
        __syncthreads();
    }

    // ---- epilogue ----
    float* plane; size_t rowbase;
    if (type == 0)      { plane = g_out1; rowbase = (size_t)sub * B_SIZE + b0; }
    else if (type == 1) { plane = g_p2;   rowbase = (size_t)sub * B_SIZE + b0; }
    else                { plane = g_H;    rowbase = (size_t)b0; }

    const float* sbias = (const float*)smem;
    const int lr = lane >> 2, lc = (lane & 3) * 2;
#pragma unroll
    for (int mi = 0; mi < 2; mi++) {
        const size_t r0 = rowbase + warpM + mi * 16 + lr;
#pragma unroll
        for (int ni = 0; ni < 8; ni++) {
            const int colLocal = warpN + ni * 8 + lc;
            const int f = f0 + colLocal;
            const float bi0 = sbias[colLocal], bi1 = sbias[colLocal + 1];
            float2 v0 = {acc[mi][ni][0] * DSCALE + bi0, acc[mi][ni][1] * DSCALE + bi1};
            float2 v1 = {acc[mi][ni][2] * DSCALE + bi0, acc[mi][ni][3] * DSCALE + bi1};
            *(float2*)(plane + r0 * NF + f)       = v0;
            *(float2*)(plane + (r0 + 8) * NF + f) = v1;
        }
    }
}

// ---------------- stats / finalize / final ----------------
__global__ __launch_bounds__(128) void stats_kernel() {
    const int f  = blockIdx.x * 128 + threadIdx.x;
    const int b0 = blockIdx.y * 128;
    double s[6] = {0, 0, 0, 0, 0, 0};
    double q[6] = {0, 0, 0, 0, 0, 0};
    for (int bb = 0; bb < 128; bb++) {
        const int b = b0 + bb;
        float o0 = g_out1[(size_t)b * NF + f];
        float o1 = g_out1[((size_t)B_SIZE + b) * NF + f];
        float h  = g_H[(size_t)b * NF + f];
        s[0] += o0; q[0] += (double)o0 * o0;
        s[1] += o1; q[1] += (double)o1 * o1;
#pragma unroll
        for (int k = 0; k < 4; k++) {
            float v = h + g_p2[((size_t)k * B_SIZE + b) * NF + f];
            s[2 + k] += v; q[2 + k] += (double)v * v;
        }
    }
#pragma unroll
    for (int w = 0; w < 6; w++) {
        atomicAdd(&g_sum[w * NF + f], s[w]);
        atomicAdd(&g_sq [w * NF + f], q[w]);
    }
}

__global__ void bn_finalize_kernel(
    const float* __restrict__ g1, const float* __restrict__ be1,
    const float* __restrict__ g2, const float* __restrict__ be2)
{
    int c = blockIdx.x * blockDim.x + threadIdx.x;
    if (c >= NWIN * NF) return;
    int w = c >> 9;
    int f = c & (NF - 1);
    double mean = g_sum[c] / (double)B_SIZE;
    double var  = g_sq[c] / (double)B_SIZE - mean * mean;
    float gamma = (w < 2) ? g1[f] : g2[f];
    float beta  = (w < 2) ? be1[f] : be2[f];
    double istd = rsqrt(var + BN_EPS);
    float sc = (float)(gamma * istd);
    g_scale[c] = sc;
    g_shift[c] = beta - (float)(mean * (double)sc);
}

__global__ __launch_bounds__(128) void final_kernel(
    const float* __restrict__ fc_w,
    const float* __restrict__ fc_b,
    float* __restrict__ out)
{
    const int b   = blockIdx.x;
    const int tid = threadIdx.x;
    const int f   = tid * 4;

    float4 o0 = *(const float4*)&g_out1[(size_t)b * NF + f];
    float4 o1 = *(const float4*)&g_out1[((size_t)B_SIZE + b) * NF + f];
    float4 h  = *(const float4*)&g_H[(size_t)b * NF + f];
    float4 p[4];
#pragma unroll
    for (int k = 0; k < 4; k++)
        p[k] = *(const float4*)&g_p2[((size_t)k * B_SIZE + b) * NF + f];

    float acc = 0.f;
#pragma unroll
    for (int l = 0; l < 4; l++) {
        const int fl = f + l;
        float x0 = (l == 0 ? o0.x : l == 1 ? o0.y : l == 2 ? o0.z : o0.w);
        float x1 = (l == 0 ? o1.x : l == 1 ? o1.y : l == 2 ? o1.z : o1.w);
        float hh = (l == 0 ? h.x  : l == 1 ? h.y  : l == 2 ? h.z  : h.w);
        float m = fmaxf(0.f, x0 * g_scale[0 * NF + fl] + g_shift[0 * NF + fl]);
        m = fminf(m, fmaxf(0.f, x1 * g_scale[1 * NF + fl] + g_shift[1 * NF + fl]));
#pragma unroll
        for (int k = 0; k < 4; k++) {
            float pk = (l == 0 ? p[k].x : l == 1 ? p[k].y : l == 2 ? p[k].z : p[k].w);
            float v = hh + pk;
            m = fminf(m, fmaxf(0.f, v * g_scale[(2 + k) * NF + fl] + g_shift[(2 + k) * NF + fl]));
        }
        acc += fc_w[fl] * m;
    }

    __shared__ float red[4];
#pragma unroll
    for (int o = 16; o > 0; o >>= 1) acc += __shfl_down_sync(0xFFFFFFFFu, acc, o);
    if ((tid & 31) == 0) red[tid >> 5] = acc;
    __syncthreads();
    if (tid == 0) out[b] = red[0] + red[1] + red[2] + red[3] + fc_b[0];
}

// ---------------- launch ----------------
extern "C" void kernel_launch(void* const* d_in, const int* in_sizes, int n_in,
                              void* d_out, int out_size) {
    int o = (in_sizes[1] == 1) ? 1 : 0;  // skip scalar arity if present
    const int*   x      = (const int*)  d_in[0];
    const float* emb_r  = (const float*)d_in[1 + o];
    const float* emb_v  = (const float*)d_in[2 + o];
    const float* w1     = (const float*)d_in[3 + o];
    const float* b1     = (const float*)d_in[4 + o];
    const float* bn1_g  = (const float*)d_in[5 + o];
    const float* bn1_b  = (const float*)d_in[6 + o];
    const float* w2     = (const float*)d_in[7 + o];
    const float* b2     = (const float*)d_in[8 + o];
    const float* bn2_g  = (const float*)d_in[9 + o];
    const float* bn2_b  = (const float*)d_in[10 + o];
    const float* fc_w   = (const float*)d_in[11 + o];
    const float* fc_b   = (const float*)d_in[12 + o];
    float* out = (float*)d_out;

    cudaFuncSetAttribute(gemm_kernel, cudaFuncAttributeMaxDynamicSharedMemorySize, SMEM_TOTAL);

    const int nre = in_sizes[1 + o];  // NR*E
    const int nve = in_sizes[2 + o];  // NV*E

    prep_tables_kernel<<<2048, 256>>>(emb_r, emb_v, nre, nve);
    prep_w_kernel<<<1024, 256>>>(w1, w2);
    zero_stats_kernel<<<(NWIN * NF + 255) / 256, 256>>>();

    gemm_kernel<<<dim3(1792, 4), 256, SMEM_TOTAL>>>(x, b1, b2);

    stats_kernel<<<dim3(NF / 128, B_SIZE / 128), 128>>>();
    bn_finalize_kernel<<<(NWIN * NF + 255) / 256, 256>>>(bn1_g, bn1_b, bn2_g, bn2_b);
    final_kernel<<<B_SIZE, 128>>>(fc_w, fc_b, out);
}

// round 9
// speedup vs baseline: 8.4931x; 1.6291x over previous
#include <cuda_runtime.h>
#include <cuda_fp16.h>
#include <math.h>
#include <stdint.h>

#define B_SIZE 32768
#define E_DIM  256
#define NF     512
#define NWIN   6
#define BN_EPS 1e-5
#define KCAT   1792   // 512 (type0) + 512 (type1) + 768 (typeH)
#define NRV    50000
#define ASCALE 256.0f
#define DSCALE (1.0f / 256.0f)

// ---------------- scratch (static device arrays) ----------------
__device__ float  g_out1[(size_t)2 * B_SIZE * NF];   // windows 0,1 (with bias)
__device__ float  g_H   [(size_t)B_SIZE * NF];       // H + b2
__device__ float  g_out2[(size_t)4 * B_SIZE * NF];   // windows 2..5 complete (H + p2)
__device__ float  g_sumf[NWIN * NF];
__device__ float  g_sqf [NWIN * NF];
__device__ float  g_scale[NWIN * NF];
__device__ float  g_shift[NWIN * NF];

// fp16 split tables (scaled x256) / fp16 weights (unscaled)
__device__ __half g_er_hi[(size_t)NRV * E_DIM];
__device__ __half g_er_lo[(size_t)NRV * E_DIM];
__device__ __half g_ev_hi[(size_t)NRV * E_DIM];
__device__ __half g_ev_lo[(size_t)NRV * E_DIM];
__device__ __half g_w_h [(size_t)NF * KCAT];

// ---------------- helpers ----------------
__device__ __forceinline__ uint32_t smem_u32(const void* p) {
    uint32_t a;
    asm("{ .reg .u64 t; cvta.to.shared.u64 t, %1; cvt.u32.u64 %0, t; }" : "=r"(a) : "l"(p));
    return a;
}
__device__ __forceinline__ void cp16(uint32_t dst, const void* src) {
    asm volatile("cp.async.cg.shared.global [%0], [%1], 16;" :: "r"(dst), "l"(src));
}
__device__ __forceinline__ void ldsm4(uint32_t& r0, uint32_t& r1, uint32_t& r2, uint32_t& r3,
                                      uint32_t addr) {
    asm volatile("ldmatrix.sync.aligned.m8n8.x4.shared.b16 {%0,%1,%2,%3}, [%4];"
                 : "=r"(r0), "=r"(r1), "=r"(r2), "=r"(r3) : "r"(addr));
}
__device__ __forceinline__ void mma16816(float* d, const uint32_t* a, uint32_t b0, uint32_t b1) {
    asm volatile(
        "mma.sync.aligned.m16n8k16.row.col.f32.f16.f16.f32 "
        "{%0,%1,%2,%3}, {%4,%5,%6,%7}, {%8,%9}, {%0,%1,%2,%3};"
        : "+f"(d[0]), "+f"(d[1]), "+f"(d[2]), "+f"(d[3])
        : "r"(a[0]), "r"(a[1]), "r"(a[2]), "r"(a[3]), "r"(b0), "r"(b1));
}

// ---------------- prep kernels ----------------
__global__ void prep_tables_kernel(const float* __restrict__ er,
                                   const float* __restrict__ ev,
                                   int nre, int nve) {
    int total = nre + nve;
    for (int i = blockIdx.x * blockDim.x + threadIdx.x; i < total; i += gridDim.x * blockDim.x) {
        if (i < nre) {
            float x = er[i] * ASCALE;
            __half hi = __float2half_rn(x);
            g_er_hi[i] = hi;
            g_er_lo[i] = __float2half_rn(x - __half2float(hi));
        } else {
            int j = i - nre;
            float x = ev[j] * ASCALE;
            __half hi = __float2half_rn(x);
            g_ev_hi[j] = hi;
            g_ev_lo[j] = __float2half_rn(x - __half2float(hi));
        }
    }
}

__global__ void prep_w_kernel(const float* __restrict__ w1, const float* __restrict__ w2) {
    for (int i = blockIdx.x * blockDim.x + threadIdx.x; i < NF * KCAT; i += gridDim.x * blockDim.x) {
        int f = i / KCAT, k = i % KCAT;
        float v;
        if      (k < 256)  v = w1[((size_t)f * 2 + 0) * E_DIM + k];
        else if (k < 512)  v = w1[((size_t)f * 2 + 1) * E_DIM + (k - 256)];
        else if (k < 768)  v = w2[((size_t)f * 5 + 3) * E_DIM + (k - 512)];
        else if (k < 1024) v = w2[((size_t)f * 5 + 4) * E_DIM + (k - 768)];
        else if (k < 1280) v = w2[((size_t)f * 5 + 0) * E_DIM + (k - 1024)];
        else if (k < 1536) v = w2[((size_t)f * 5 + 1) * E_DIM + (k - 1280)];
        else               v = w2[((size_t)f * 5 + 2) * E_DIM + (k - 1536)];
        g_w_h[i] = __float2half_rn(v);
    }
}

__global__ void zero_stats_kernel() {
    int i = blockIdx.x * blockDim.x + threadIdx.x;
    if (i < NWIN * NF) { g_sumf[i] = 0.f; g_sqf[i] = 0.f; }
}

// ---------------- GEMM kernel (mma.sync fp16, A-split 2-MMA) ----------------
// phase 0: typeH, grid (256, 4)  -> writes g_H (= H + b2)
// phase 1: type0/1, grid (1536, 4) -> writes g_out1 / g_out2(+H), computes BN stats
// block 256 (8 warps, 4x2; warp tile 32x64), 2 CTAs/SM target.
// smem: [0,512) bias; [512,1536) stats red (2x128 floats); stages at 4096, 2 x 48KB.
#define SM_RED      512
#define SM_STAGE0   4096
#define STAGE_BYTES 49152
#define SMEM_TOTAL  (SM_STAGE0 + 2 * STAGE_BYTES)

__global__ __launch_bounds__(256, 2) void gemm_kernel(
    const int phase,
    const int* __restrict__ x,
    const float* __restrict__ bvec)   // b1 for phase1(type0), b2 for phase0; indexed per type
{
    extern __shared__ char smem[];
    const uint32_t sb = smem_u32(smem);
    const int tid = threadIdx.x, wid = tid >> 5, lane = tid & 31;
    const int f0 = blockIdx.y * 128;

    int type, sub, b0, nch, kbase;
    if (phase == 0) { type = 2; sub = 0; b0 = blockIdx.x * 128; nch = 12; kbase = 1024; }
    else {
        const int tile = blockIdx.x;
        if (tile < 512) { type = 0; sub = tile >> 8;         b0 = (tile & 255) * 128;         nch = 8; kbase = 0; }
        else            { type = 1; sub = (tile - 512) >> 8; b0 = ((tile - 512) & 255) * 128; nch = 8; kbase = 512; }
    }

    {
        const float* bp = (type == 1) ? (const float*)0 : bvec;
        float* sbias = (float*)smem;
        if (tid < 128) sbias[tid] = bp ? bp[f0 + tid] : 0.0f;
        float* sred = (float*)(smem + SM_RED);
        if (tid < 256) sred[tid] = 0.0f;
    }

    // ---- chunk loader (cp.async gather) ----
    const int row = tid >> 1, half2 = tid & 1;
    auto issue_loads = [&](int cc) {
        const uint32_t tb = sb + SM_STAGE0 + (uint32_t)(cc & 1) * STAGE_BYTES;
        // A row gather (hi+lo)
        {
            const int cq = cc >> 2, e0 = (cc & 3) * 64;
            int col; const __half *th, *tl;
            if (type == 0) {
                if (cq == 0) { col = 2 * sub + 1; th = g_ev_hi; tl = g_ev_lo; }
                else         { col = 0;           th = g_er_hi; tl = g_er_lo; }
            } else if (type == 1) {
                if (cq == 0) { col = 4 + 2 * sub; th = g_er_hi; tl = g_er_lo; }
                else         { col = 5 + 2 * sub; th = g_ev_hi; tl = g_ev_lo; }
            } else {
                if (cq == 0)      { col = 1; th = g_ev_hi; tl = g_ev_lo; }
                else if (cq == 1) { col = 0; th = g_er_hi; tl = g_er_lo; }
                else              { col = 3; th = g_ev_hi; tl = g_ev_lo; }
            }
            const int idx = __ldg(x + (size_t)(b0 + row) * 12 + col);
            const char* sh = (const char*)(th + (size_t)idx * E_DIM + e0);
            const char* sl = (const char*)(tl + (size_t)idx * E_DIM + e0);
            const uint32_t ro = (uint32_t)row * 128;
            const uint32_t xr = (uint32_t)(row & 7);
#pragma unroll
            for (int g = 0; g < 4; g++) {
                const int gg = half2 * 4 + g;
                const uint32_t so = ro + (uint32_t)((gg ^ xr) * 16);
                cp16(tb + so,         sh + gg * 16);
                cp16(tb + 16384 + so, sl + gg * 16);
            }
        }
        // B rows (feature f0+row)
        {
            const char* ph = (const char*)(g_w_h + (size_t)(f0 + row) * KCAT + kbase + cc * 64);
            const uint32_t ro = (uint32_t)row * 128;
            const uint32_t xr = (uint32_t)(row & 7);
#pragma unroll
            for (int g = 0; g < 4; g++) {
                const int gg = half2 * 4 + g;
                const uint32_t so = ro + (uint32_t)((gg ^ xr) * 16);
                cp16(tb + 32768 + so, ph + gg * 16);
            }
        }
        asm volatile("cp.async.commit_group;" ::: "memory");
    };

    // ---- per-warp frag addressing ----
    const int warpM = (wid & 3) * 32;
    const int warpN = (wid >> 2) * 64;
    uint32_t aOff[2], aXor[2];
#pragma unroll
    for (int mi = 0; mi < 2; mi++) {
        const int r = warpM + mi * 16 + (lane & 15);
        aOff[mi] = (uint32_t)r * 128;
        aXor[mi] = (uint32_t)(r & 7);
    }
    const uint32_t aSel = (uint32_t)((lane >> 4) & 1);
    uint32_t bOff[4], bXor[4];
#pragma unroll
    for (int p = 0; p < 4; p++) {
        const int r = warpN + p * 16 + (lane & 7) + (((lane >> 4) & 1) << 3);
        bOff[p] = (uint32_t)r * 128;
        bXor[p] = (uint32_t)(r & 7);
    }
    const uint32_t bSel = (uint32_t)((lane >> 3) & 1);

    float acc[2][8][4];
#pragma unroll
    for (int mi = 0; mi < 2; mi++)
#pragma unroll
        for (int ni = 0; ni < 8; ni++)
#pragma unroll
            for (int q = 0; q < 4; q++) acc[mi][ni][q] = 0.f;

    issue_loads(0);

    for (int c = 0; c < nch; c++) {
        if (c + 1 < nch) { issue_loads(c + 1); asm volatile("cp.async.wait_group 1;" ::: "memory"); }
        else             {                     asm volatile("cp.async.wait_group 0;" ::: "memory"); }
        __syncthreads();

        const uint32_t tb = sb + SM_STAGE0 + (uint32_t)(c & 1) * STAGE_BYTES;
#pragma unroll
        for (int s = 0; s < 4; s++) {
            uint32_t fah[2][4], fal[2][4], fb[4][4];
            const uint32_t blk = (uint32_t)(2 * s);
#pragma unroll
            for (int mi = 0; mi < 2; mi++) {
                const uint32_t ad = tb + aOff[mi] + (((blk + aSel) ^ aXor[mi]) * 16);
                ldsm4(fah[mi][0], fah[mi][1], fah[mi][2], fah[mi][3], ad);
                ldsm4(fal[mi][0], fal[mi][1], fal[mi][2], fal[mi][3], ad + 16384);
            }
#pragma unroll
            for (int p = 0; p < 4; p++) {
                const uint32_t bd = tb + 32768 + bOff[p] + (((blk + bSel) ^ bXor[p]) * 16);
                ldsm4(fb[p][0], fb[p][1], fb[p][2], fb[p][3], bd);
            }
#pragma unroll
            for (int mi = 0; mi < 2; mi++)
#pragma unroll
                for (int ni = 0; ni < 8; ni++) {
                    const int p = ni >> 1, o = (ni & 1) * 2;
                    mma16816(acc[mi][ni], fah[mi], fb[p][o], fb[p][o + 1]);
                    mma16816(acc[mi][ni], fal[mi], fb[p][o], fb[p][o + 1]);
                }
        }
        __syncthreads();
    }

    // ---- epilogue ----
    const float* sbias = (const float*)smem;
    float* sred = (float*)(smem + SM_RED);
    const int lr = lane >> 2, lc = (lane & 3) * 2;
    const int nhalf = wid >> 2;

    if (type == 2) {
        // write H plane (includes b2)
#pragma unroll
        for (int mi = 0; mi < 2; mi++) {
            const size_t r0 = (size_t)b0 + warpM + mi * 16 + lr;
#pragma unroll
            for (int ni = 0; ni < 8; ni++) {
                const int colLocal = warpN + ni * 8 + lc;
                const int f = f0 + colLocal;
                const float bi0 = sbias[colLocal], bi1 = sbias[colLocal + 1];
                float2 v0 = {acc[mi][ni][0] * DSCALE + bi0, acc[mi][ni][1] * DSCALE + bi1};
                float2 v1 = {acc[mi][ni][2] * DSCALE + bi0, acc[mi][ni][3] * DSCALE + bi1};
                *(float2*)(g_H + r0 * NF + f)       = v0;
                *(float2*)(g_H + (r0 + 8) * NF + f) = v1;
            }
        }
        return;
    }

    const int w = (type == 0) ? sub : (2 + sub);
    float* plane = (type == 0) ? g_out1 : g_out2;
    const size_t rowbase = (size_t)sub * B_SIZE + b0;

#pragma unroll
    for (int ni = 0; ni < 8; ni++) {
        const int colLocal = warpN + ni * 8 + lc;
        const int f = f0 + colLocal;
        const float bi0 = sbias[colLocal], bi1 = sbias[colLocal + 1];
        float s0 = 0.f, q0 = 0.f, s1 = 0.f, q1 = 0.f;
#pragma unroll
        for (int mi = 0; mi < 2; mi++) {
            const size_t hr0 = (size_t)b0 + warpM + mi * 16 + lr;
            float v00 = acc[mi][ni][0] * DSCALE + bi0;
            float v01 = acc[mi][ni][1] * DSCALE + bi1;
            float v10 = acc[mi][ni][2] * DSCALE + bi0;
            float v11 = acc[mi][ni][3] * DSCALE + bi1;
            if (type == 1) {
                float2 h0 = *(const float2*)(g_H + hr0 * NF + f);
                float2 h1 = *(const float2*)(g_H + (hr0 + 8) * NF + f);
                v00 += h0.x; v01 += h0.y; v10 += h1.x; v11 += h1.y;
            }
            const size_t r0 = rowbase + warpM + mi * 16 + lr;
            *(float2*)(plane + r0 * NF + f)       = make_float2(v00, v01);
            *(float2*)(plane + (r0 + 8) * NF + f) = make_float2(v10, v11);
            s0 += v00 + v10; q0 += v00 * v00 + v10 * v10;
            s1 += v01 + v11; q1 += v01 * v01 + v11 * v11;
        }
        // reduce over the 8 row-groups (lane bits 2..4)
#pragma unroll
        for (int off = 4; off < 32; off <<= 1) {
            s0 += __shfl_xor_sync(0xFFFFFFFFu, s0, off);
            q0 += __shfl_xor_sync(0xFFFFFFFFu, q0, off);
            s1 += __shfl_xor_sync(0xFFFFFFFFu, s1, off);
            q1 += __shfl_xor_sync(0xFFFFFFFFu, q1, off);
        }
        if (lane < 4) {
            const int cl = nhalf * 64 + ni * 8 + lane * 2;
            atomicAdd(&sred[cl], s0);       atomicAdd(&sred[128 + cl], q0);
            atomicAdd(&sred[cl + 1], s1);   atomicAdd(&sred[128 + cl + 1], q1);
        }
    }
    __syncthreads();
    if (tid < 128)      atomicAdd(&g_sumf[w * NF + f0 + tid], sred[tid]);
    else if (tid < 256) atomicAdd(&g_sqf [w * NF + f0 + (tid - 128)], sred[tid]);
}

// ---------------- finalize scale/shift ----------------
__global__ void bn_finalize_kernel(
    const float* __restrict__ g1, const float* __restrict__ be1,
    const float* __restrict__ g2, const float* __restrict__ be2)
{
    int c = blockIdx.x * blockDim.x + threadIdx.x;
    if (c >= NWIN * NF) return;
    int w = c >> 9;
    int f = c & (NF - 1);
    double mean = (double)g_sumf[c] / (double)B_SIZE;
    double var  = (double)g_sqf[c] / (double)B_SIZE - mean * mean;
    float gamma = (w < 2) ? g1[f] : g2[f];
    float beta  = (w < 2) ? be1[f] : be2[f];
    double istd = rsqrt(var + BN_EPS);
    float sc = (float)(gamma * istd);
    g_scale[c] = sc;
    g_shift[c] = beta - (float)(mean * (double)sc);
}

// ---------------- BN + relu + min + fc ----------------
__global__ __launch_bounds__(128) void final_kernel(
    const float* __restrict__ fc_w,
    const float* __restrict__ fc_b,
    float* __restrict__ out)
{
    const int b   = blockIdx.x;
    const int tid = threadIdx.x;
    const int f   = tid * 4;

    float4 o0 = *(const float4*)&g_out1[(size_t)b * NF + f];
    float4 o1 = *(const float4*)&g_out1[((size_t)B_SIZE + b) * NF + f];
    float4 p[4];
#pragma unroll
    for (int k = 0; k < 4; k++)
        p[k] = *(const float4*)&g_out2[((size_t)k * B_SIZE + b) * NF + f];

    float acc = 0.f;
#pragma unroll
    for (int l = 0; l < 4; l++) {
        const int fl = f + l;
        float x0 = (l == 0 ? o0.x : l == 1 ? o0.y : l == 2 ? o0.z : o0.w);
        float x1 = (l == 0 ? o1.x : l == 1 ? o1.y : l == 2 ? o1.z : o1.w);
        float m = fmaxf(0.f, x0 * g_scale[0 * NF + fl] + g_shift[0 * NF + fl]);
        m = fminf(m, fmaxf(0.f, x1 * g_scale[1 * NF + fl] + g_shift[1 * NF + fl]));
#pragma unroll
        for (int k = 0; k < 4; k++) {
            float pk = (l == 0 ? p[k].x : l == 1 ? p[k].y : l == 2 ? p[k].z : p[k].w);
            m = fminf(m, fmaxf(0.f, pk * g_scale[(2 + k) * NF + fl] + g_shift[(2 + k) * NF + fl]));
        }
        acc += fc_w[fl] * m;
    }

    __shared__ float red[4];
#pragma unroll
    for (int o = 16; o > 0; o >>= 1) acc += __shfl_down_sync(0xFFFFFFFFu, acc, o);
    if ((tid & 31) == 0) red[tid >> 5] = acc;
    __syncthreads();
    if (tid == 0) out[b] = red[0] + red[1] + red[2] + red[3] + fc_b[0];
}

// ---------------- launch ----------------
extern "C" void kernel_launch(void* const* d_in, const int* in_sizes, int n_in,
                              void* d_out, int out_size) {
    int o = (in_sizes[1] == 1) ? 1 : 0;  // skip scalar arity if present
    const int*   x      = (const int*)  d_in[0];
    const float* emb_r  = (const float*)d_in[1 + o];
    const float* emb_v  = (const float*)d_in[2 + o];
    const float* w1     = (const float*)d_in[3 + o];
    const float* b1     = (const float*)d_in[4 + o];
    const float* bn1_g  = (const float*)d_in[5 + o];
    const float* bn1_b  = (const float*)d_in[6 + o];
    const float* w2     = (const float*)d_in[7 + o];
    const float* b2     = (const float*)d_in[8 + o];
    const float* bn2_g  = (const float*)d_in[9 + o];
    const float* bn2_b  = (const float*)d_in[10 + o];
    const float* fc_w   = (const float*)d_in[11 + o];
    const float* fc_b   = (const float*)d_in[12 + o];
    float* out = (float*)d_out;

    cudaFuncSetAttribute(gemm_kernel, cudaFuncAttributeMaxDynamicSharedMemorySize, SMEM_TOTAL);

    const int nre = in_sizes[1 + o];  // NR*E
    const int nve = in_sizes[2 + o];  // NV*E

    prep_tables_kernel<<<2048, 256>>>(emb_r, emb_v, nre, nve);
    prep_w_kernel<<<1024, 256>>>(w1, w2);
    zero_stats_kernel<<<(NWIN * NF + 255) / 256, 256>>>();

    // phase 0: typeH -> g_H
    gemm_kernel<<<dim3(256, 4), 256, SMEM_TOTAL>>>(0, x, b2);
    // phase 1: type0/1 -> planes + stats (reads g_H)
    gemm_kernel<<<dim3(1536, 4), 256, SMEM_TOTAL>>>(1, x, b1);

    bn_finalize_kernel<<<(NWIN * NF + 255) / 256, 256>>>(bn1_g, bn1_b, bn2_g, bn2_b);
    final_kernel<<<B_SIZE, 128>>>(fc_w, fc_b, out);
}

// round 11
// speedup vs baseline: 8.5741x; 1.0095x over previous
#include <cuda_runtime.h>
#include <cuda_fp16.h>
#include <math.h>
#include <stdint.h>

#define B_SIZE 32768
#define E_DIM  256
#define NF     512
#define NWIN   6
#define BN_EPS 1e-5
#define KCAT   1792   // 512 (type0) + 512 (type1) + 768 (typeH)
#define NRV    50000
#define ASCALE 256.0f
#define DSCALE (1.0f / 256.0f)

// ---------------- scratch (static device arrays) ----------------
__device__ float  g_out1[(size_t)2 * B_SIZE * NF];   // windows 0,1 (with bias)
__device__ float  g_H   [(size_t)B_SIZE * NF];       // H + b2
__device__ float  g_out2[(size_t)4 * B_SIZE * NF];   // windows 2..5 complete (H + p2)
__device__ float  g_sumf[NWIN * NF];
__device__ float  g_sqf [NWIN * NF];
__device__ float  g_scale[NWIN * NF];
__device__ float  g_shift[NWIN * NF];

// fp16 split tables (scaled x256) / fp16 weights (unscaled)
__device__ __half g_er_hi[(size_t)NRV * E_DIM];
__device__ __half g_er_lo[(size_t)NRV * E_DIM];
__device__ __half g_ev_hi[(size_t)NRV * E_DIM];
__device__ __half g_ev_lo[(size_t)NRV * E_DIM];
__device__ __half g_w_h [(size_t)NF * KCAT];

// ---------------- helpers ----------------
__device__ __forceinline__ uint32_t smem_u32(const void* p) {
    uint32_t a;
    asm("{ .reg .u64 t; cvta.to.shared.u64 t, %1; cvt.u32.u64 %0, t; }" : "=r"(a) : "l"(p));
    return a;
}
__device__ __forceinline__ void cp16(uint32_t dst, const void* src) {
    asm volatile("cp.async.cg.shared.global [%0], [%1], 16;" :: "r"(dst), "l"(src));
}
__device__ __forceinline__ void ldsm4(uint32_t& r0, uint32_t& r1, uint32_t& r2, uint32_t& r3,
                                      uint32_t addr) {
    asm volatile("ldmatrix.sync.aligned.m8n8.x4.shared.b16 {%0,%1,%2,%3}, [%4];"
                 : "=r"(r0), "=r"(r1), "=r"(r2), "=r"(r3) : "r"(addr));
}
__device__ __forceinline__ void mma16816(float* d, const uint32_t* a, uint32_t b0, uint32_t b1) {
    asm volatile(
        "mma.sync.aligned.m16n8k16.row.col.f32.f16.f16.f32 "
        "{%0,%1,%2,%3}, {%4,%5,%6,%7}, {%8,%9}, {%0,%1,%2,%3};"
        : "+f"(d[0]), "+f"(d[1]), "+f"(d[2]), "+f"(d[3])
        : "r"(a[0]), "r"(a[1]), "r"(a[2]), "r"(a[3]), "r"(b0), "r"(b1));
}

// ---------------- prep kernels ----------------
__global__ void prep_tables_kernel(const float* __restrict__ er,
                                   const float* __restrict__ ev,
                                   int nre, int nve) {
    int total = nre + nve;
    for (int i = blockIdx.x * blockDim.x + threadIdx.x; i < total; i += gridDim.x * blockDim.x) {
        if (i < nre) {
            float x = er[i] * ASCALE;
            __half hi = __float2half_rn(x);
            g_er_hi[i] = hi;
            g_er_lo[i] = __float2half_rn(x - __half2float(hi));
        } else {
            int j = i - nre;
            float x = ev[j] * ASCALE;
            __half hi = __float2half_rn(x);
            g_ev_hi[j] = hi;
            g_ev_lo[j] = __float2half_rn(x - __half2float(hi));
        }
    }
}

__global__ void prep_w_kernel(const float* __restrict__ w1, const float* __restrict__ w2) {
    for (int i = blockIdx.x * blockDim.x + threadIdx.x; i < NF * KCAT; i += gridDim.x * blockDim.x) {
        int f = i / KCAT, k = i % KCAT;
        float v;
        if      (k < 256)  v = w1[((size_t)f * 2 + 0) * E_DIM + k];
        else if (k < 512)  v = w1[((size_t)f * 2 + 1) * E_DIM + (k - 256)];
        else if (k < 768)  v = w2[((size_t)f * 5 + 3) * E_DIM + (k - 512)];
        else if (k < 1024) v = w2[((size_t)f * 5 + 4) * E_DIM + (k - 768)];
        else if (k < 1280) v = w2[((size_t)f * 5 + 0) * E_DIM + (k - 1024)];
        else if (k < 1536) v = w2[((size_t)f * 5 + 1) * E_DIM + (k - 1280)];
        else               v = w2[((size_t)f * 5 + 2) * E_DIM + (k - 1536)];
        g_w_h[i] = __float2half_rn(v);
    }
}

__global__ void zero_stats_kernel() {
    int i = blockIdx.x * blockDim.x + threadIdx.x;
    if (i < NWIN * NF) { g_sumf[i] = 0.f; g_sqf[i] = 0.f; }
}

// ---------------- GEMM kernel (mma.sync fp16, A-split 2-MMA) ----------------
// phase 0: typeH, grid (256, 4)  -> writes g_H (= H + b2)
// phase 1: type0/1, grid (1536, 4) -> writes g_out1 / g_out2(+H), computes BN stats
// block 256 (8 warps, 4x2; warp tile 32x64), 2 CTAs/SM.
// smem: [0,512) bias; [512,1536) stats red; stages at 4096, 2 x 48KB.
// Single barrier per chunk: wait(c) ; sync ; issue(c+1) ; mma(c).
#define SM_RED      512
#define SM_STAGE0   4096
#define STAGE_BYTES 49152
#define SMEM_TOTAL  (SM_STAGE0 + 2 * STAGE_BYTES)

__global__ __launch_bounds__(256, 2) void gemm_kernel(
    const int phase,
    const int* __restrict__ x,
    const float* __restrict__ bvec)
{
    extern __shared__ char smem[];
    const uint32_t sb = smem_u32(smem);
    const int tid = threadIdx.x, wid = tid >> 5, lane = tid & 31;
    const int f0 = blockIdx.y * 128;

    int type, sub, b0, nch, kbase;
    if (phase == 0) { type = 2; sub = 0; b0 = blockIdx.x * 128; nch = 12; kbase = 1024; }
    else {
        const int tile = blockIdx.x;
        if (tile < 512) { type = 0; sub = tile >> 8;         b0 = (tile & 255) * 128;         nch = 8; kbase = 0; }
        else            { type = 1; sub = (tile - 512) >> 8; b0 = ((tile - 512) & 255) * 128; nch = 8; kbase = 512; }
    }

    {
        const float* bp = (type == 1) ? (const float*)0 : bvec;
        float* sbias = (float*)smem;
        if (tid < 128) sbias[tid] = bp ? bp[f0 + tid] : 0.0f;
        float* sred = (float*)(smem + SM_RED);
        if (tid < 256) sred[tid] = 0.0f;
    }

    // ---- gather setup: hoist per-cq index loads ----
    const int row = tid >> 1, half2 = tid & 1;
    const __half* Ath[3];
    const __half* Atl[3];
    int aidx[3] = {0, 0, 0};
    {
        int cols[3] = {0, 0, 0};
        int ncq;
        if (type == 0)      { cols[0] = 2 * sub + 1; Ath[0] = g_ev_hi; Atl[0] = g_ev_lo;
                              cols[1] = 0;           Ath[1] = g_er_hi; Atl[1] = g_er_lo; ncq = 2; Ath[2] = g_er_hi; Atl[2] = g_er_lo; }
        else if (type == 1) { cols[0] = 4 + 2 * sub; Ath[0] = g_er_hi; Atl[0] = g_er_lo;
                              cols[1] = 5 + 2 * sub; Ath[1] = g_ev_hi; Atl[1] = g_ev_lo; ncq = 2; Ath[2] = g_ev_hi; Atl[2] = g_ev_lo; }
        else                { cols[0] = 1; Ath[0] = g_ev_hi; Atl[0] = g_ev_lo;
                              cols[1] = 0; Ath[1] = g_er_hi; Atl[1] = g_er_lo;
                              cols[2] = 3; Ath[2] = g_ev_hi; Atl[2] = g_ev_lo; ncq = 3; }
        const int* xrow = x + (size_t)(b0 + row) * 12;
#pragma unroll
        for (int q = 0; q < 3; q++)
            if (q < ncq) aidx[q] = __ldg(xrow + cols[q]);
    }

    auto issue_loads = [&](int cc) {
        const uint32_t tb = sb + SM_STAGE0 + (uint32_t)(cc & 1) * STAGE_BYTES;
        const uint32_t ro = (uint32_t)row * 128;
        const uint32_t xr = (uint32_t)(row & 7);
        // A row gather (hi+lo)
        {
            const int cq = cc >> 2, e0 = (cc & 3) * 64;
            const char* sh = (const char*)(Ath[cq] + (size_t)aidx[cq] * E_DIM + e0);
            const char* sl = (const char*)(Atl[cq] + (size_t)aidx[cq] * E_DIM + e0);
#pragma unroll
            for (int g = 0; g < 4; g++) {
                const int gg = half2 * 4 + g;
                const uint32_t so = ro + (uint32_t)((gg ^ xr) * 16);
                cp16(tb + so,         sh + gg * 16);
                cp16(tb + 16384 + so, sl + gg * 16);
            }
        }
        // B rows (feature f0+row)
        {
            const char* ph = (const char*)(g_w_h + (size_t)(f0 + row) * KCAT + kbase + cc * 64);
#pragma unroll
            for (int g = 0; g < 4; g++) {
                const int gg = half2 * 4 + g;
                const uint32_t so = ro + (uint32_t)((gg ^ xr) * 16);
                cp16(tb + 32768 + so, ph + gg * 16);
            }
        }
        asm volatile("cp.async.commit_group;" ::: "memory");
    };

    // ---- per-warp frag addressing ----
    const int warpM = (wid & 3) * 32;
    const int warpN = (wid >> 2) * 64;
    uint32_t aOff[2], aXor[2];
#pragma unroll
    for (int mi = 0; mi < 2; mi++) {
        const int r = warpM + mi * 16 + (lane & 15);
        aOff[mi] = (uint32_t)r * 128;
        aXor[mi] = (uint32_t)(r & 7);
    }
    const uint32_t aSel = (uint32_t)((lane >> 4) & 1);
    uint32_t bOff[4], bXor[4];
#pragma unroll
    for (int p = 0; p < 4; p++) {
        const int r = warpN + p * 16 + (lane & 7) + (((lane >> 4) & 1) << 3);
        bOff[p] = (uint32_t)r * 128;
        bXor[p] = (uint32_t)(r & 7);
    }
    const uint32_t bSel = (uint32_t)((lane >> 3) & 1);

    float acc[2][8][4];
#pragma unroll
    for (int mi = 0; mi < 2; mi++)
#pragma unroll
        for (int ni = 0; ni < 8; ni++)
#pragma unroll
            for (int q = 0; q < 4; q++) acc[mi][ni][q] = 0.f;

    issue_loads(0);

    for (int c = 0; c < nch; c++) {
        asm volatile("cp.async.wait_group 0;" ::: "memory");
        __syncthreads();                 // chunk c data ready; all warps done with c-1
        if (c + 1 < nch) issue_loads(c + 1);   // other buffer (last read in c-1) — safe

        const uint32_t tb = sb + SM_STAGE0 + (uint32_t)(c & 1) * STAGE_BYTES;
#pragma unroll
        for (int s = 0; s < 4; s++) {
            uint32_t fah[2][4], fal[2][4], fb[4][4];
            const uint32_t blk = (uint32_t)(2 * s);
#pragma unroll
            for (int mi = 0; mi < 2; mi++) {
                const uint32_t ad = tb + aOff[mi] + (((blk + aSel) ^ aXor[mi]) * 16);
                ldsm4(fah[mi][0], fah[mi][1], fah[mi][2], fah[mi][3], ad);
                ldsm4(fal[mi][0], fal[mi][1], fal[mi][2], fal[mi][3], ad + 16384);
            }
#pragma unroll
            for (int p = 0; p < 4; p++) {
                const uint32_t bd = tb + 32768 + bOff[p] + (((blk + bSel) ^ bXor[p]) * 16);
                ldsm4(fb[p][0], fb[p][1], fb[p][2], fb[p][3], bd);
            }
#pragma unroll
            for (int mi = 0; mi < 2; mi++)
#pragma unroll
                for (int ni = 0; ni < 8; ni++) {
                    const int p = ni >> 1, o = (ni & 1) * 2;
                    mma16816(acc[mi][ni], fah[mi], fb[p][o], fb[p][o + 1]);
                    mma16816(acc[mi][ni], fal[mi], fb[p][o], fb[p][o + 1]);
                }
        }
    }

    // ---- epilogue ----
    const float* sbias = (const float*)smem;
    float* sred = (float*)(smem + SM_RED);
    const int lr = lane >> 2, lc = (lane & 3) * 2;
    const int nhalf = wid >> 2;

    if (type == 2) {
#pragma unroll
        for (int mi = 0; mi < 2; mi++) {
            const size_t r0 = (size_t)b0 + warpM + mi * 16 + lr;
#pragma unroll
            for (int ni = 0; ni < 8; ni++) {
                const int colLocal = warpN + ni * 8 + lc;
                const int f = f0 + colLocal;
                const float bi0 = sbias[colLocal], bi1 = sbias[colLocal + 1];
                float2 v0 = {acc[mi][ni][0] * DSCALE + bi0, acc[mi][ni][1] * DSCALE + bi1};
                float2 v1 = {acc[mi][ni][2] * DSCALE + bi0, acc[mi][ni][3] * DSCALE + bi1};
                *(float2*)(g_H + r0 * NF + f)       = v0;
                *(float2*)(g_H + (r0 + 8) * NF + f) = v1;
            }
        }
        return;
    }

    const int w = (type == 0) ? sub : (2 + sub);
    float* plane = (type == 0) ? g_out1 : g_out2;
    const size_t rowbase = (size_t)sub * B_SIZE + b0;

#pragma unroll
    for (int ni = 0; ni < 8; ni++) {
        const int colLocal = warpN + ni * 8 + lc;
        const int f = f0 + colLocal;
        const float bi0 = sbias[colLocal], bi1 = sbias[colLocal + 1];
        float s0 = 0.f, q0 = 0.f, s1 = 0.f, q1 = 0.f;
#pragma unroll
        for (int mi = 0; mi < 2; mi++) {
            const size_t hr0 = (size_t)b0 + warpM + mi * 16 + lr;
            float v00 = acc[mi][ni][0] * DSCALE + bi0;
            float v01 = acc[mi][ni][1] * DSCALE + bi1;
            float v10 = acc[mi][ni][2] * DSCALE + bi0;
            float v11 = acc[mi][ni][3] * DSCALE + bi1;
            if (type == 1) {
                float2 h0 = *(const float2*)(g_H + hr0 * NF + f);
                float2 h1 = *(const float2*)(g_H + (hr0 + 8) * NF + f);
                v00 += h0.x; v01 += h0.y; v10 += h1.x; v11 += h1.y;
            }
            const size_t r0 = rowbase + warpM + mi * 16 + lr;
            *(float2*)(plane + r0 * NF + f)       = make_float2(v00, v01);
            *(float2*)(plane + (r0 + 8) * NF + f) = make_float2(v10, v11);
            s0 += v00 + v10; q0 += v00 * v00 + v10 * v10;
            s1 += v01 + v11; q1 += v01 * v01 + v11 * v11;
        }
#pragma unroll
        for (int off = 4; off < 32; off <<= 1) {
            s0 += __shfl_xor_sync(0xFFFFFFFFu, s0, off);
            q0 += __shfl_xor_sync(0xFFFFFFFFu, q0, off);
            s1 += __shfl_xor_sync(0xFFFFFFFFu, s1, off);
            q1 += __shfl_xor_sync(0xFFFFFFFFu, q1, off);
        }
        if (lane < 4) {
            const int cl = nhalf * 64 + ni * 8 + lane * 2;
            atomicAdd(&sred[cl], s0);       atomicAdd(&sred[128 + cl], q0);
            atomicAdd(&sred[cl + 1], s1);   atomicAdd(&sred[128 + cl + 1], q1);
        }
    }
    __syncthreads();
    if (tid < 128)      atomicAdd(&g_sumf[w * NF + f0 + tid], sred[tid]);
    else if (tid < 256) atomicAdd(&g_sqf [w * NF + f0 + (tid - 128)], sred[tid]);
}

// ---------------- finalize scale/shift ----------------
__global__ void bn_finalize_kernel(
    const float* __restrict__ g1, const float* __restrict__ be1,
    const float* __restrict__ g2, const float* __restrict__ be2)
{
    int c = blockIdx.x * blockDim.x + threadIdx.x;
    if (c >= NWIN * NF) return;
    int w = c >> 9;
    int f = c & (NF - 1);
    double mean = (double)g_sumf[c] / (double)B_SIZE;
    double var  = (double)g_sqf[c] / (double)B_SIZE - mean * mean;
    float gamma = (w < 2) ? g1[f] : g2[f];
    float beta  = (w < 2) ? be1[f] : be2[f];
    double istd = rsqrt(var + BN_EPS);
    float sc = (float)(gamma * istd);
    g_scale[c] = sc;
    g_shift[c] = beta - (float)(mean * (double)sc);
}

// ---------------- BN + relu + min + fc ----------------
__global__ __launch_bounds__(128) void final_kernel(
    const float* __restrict__ fc_w,
    const float* __restrict__ fc_b,
    float* __restrict__ out)
{
    const int b   = blockIdx.x;
    const int tid = threadIdx.x;
    const int f   = tid * 4;

    float4 o0 = *(const float4*)&g_out1[(size_t)b * NF + f];
    float4 o1 = *(const float4*)&g_out1[((size_t)B_SIZE + b) * NF + f];
    float4 p[4];
#pragma unroll
    for (int k = 0; k < 4; k++)
        p[k] = *(const float4*)&g_out2[((size_t)k * B_SIZE + b) * NF + f];

    float acc = 0.f;
#pragma unroll
    for (int l = 0; l < 4; l++) {
        const int fl = f + l;
        float x0 = (l == 0 ? o0.x : l == 1 ? o0.y : l == 2 ? o0.z : o0.w);
        float x1 = (l == 0 ? o1.x : l == 1 ? o1.y : l == 2 ? o1.z : o1.w);
        float m = fmaxf(0.f, x0 * g_scale[0 * NF + fl] + g_shift[0 * NF + fl]);
        m = fminf(m, fmaxf(0.f, x1 * g_scale[1 * NF + fl] + g_shift[1 * NF + fl]));
#pragma unroll
        for (int k = 0; k < 4; k++) {
            float pk = (l == 0 ? p[k].x : l == 1 ? p[k].y : l == 2 ? p[k].z : p[k].w);
            m = fminf(m, fmaxf(0.f, pk * g_scale[(2 + k) * NF + fl] + g_shift[(2 + k) * NF + fl]));
        }
        acc += fc_w[fl] * m;
    }

    __shared__ float red[4];
#pragma unroll
    for (int o = 16; o > 0; o >>= 1) acc += __shfl_down_sync(0xFFFFFFFFu, acc, o);
    if ((tid & 31) == 0) red[tid >> 5] = acc;
    __syncthreads();
    if (tid == 0) out[b] = red[0] + red[1] + red[2] + red[3] + fc_b[0];
}

// ---------------- launch ----------------
extern "C" void kernel_launch(void* const* d_in, const int* in_sizes, int n_in,
                              void* d_out, int out_size) {
    int o = (in_sizes[1] == 1) ? 1 : 0;  // skip scalar arity if present
    const int*   x      = (const int*)  d_in[0];
    const float* emb_r  = (const float*)d_in[1 + o];
    const float* emb_v  = (const float*)d_in[2 + o];
    const float* w1     = (const float*)d_in[3 + o];
    const float* b1     = (const float*)d_in[4 + o];
    const float* bn1_g  = (const float*)d_in[5 + o];
    const float* bn1_b  = (const float*)d_in[6 + o];
    const float* w2     = (const float*)d_in[7 + o];
    const float* b2     = (const float*)d_in[8 + o];
    const float* bn2_g  = (const float*)d_in[9 + o];
    const float* bn2_b  = (const float*)d_in[10 + o];
    const float* fc_w   = (const float*)d_in[11 + o];
    const float* fc_b   = (const float*)d_in[12 + o];
    float* out = (float*)d_out;

    cudaFuncSetAttribute(gemm_kernel, cudaFuncAttributeMaxDynamicSharedMemorySize, SMEM_TOTAL);

    const int nre = in_sizes[1 + o];  // NR*E
    const int nve = in_sizes[2 + o];  // NV*E

    prep_tables_kernel<<<2048, 256>>>(emb_r, emb_v, nre, nve);
    prep_w_kernel<<<1024, 256>>>(w1, w2);
    zero_stats_kernel<<<(NWIN * NF + 255) / 256, 256>>>();

    // phase 0: typeH -> g_H
    gemm_kernel<<<dim3(256, 4), 256, SMEM_TOTAL>>>(0, x, b2);
    // phase 1: type0/1 -> planes + stats (reads g_H)
    gemm_kernel<<<dim3(1536, 4), 256, SMEM_TOTAL>>>(1, x, b1);

    bn_finalize_kernel<<<(NWIN * NF + 255) / 256, 256>>>(bn1_g, bn1_b, bn2_g, bn2_b);
    final_kernel<<<B_SIZE, 128>>>(fc_w, fc_b, out);
}

// round 12
// speedup vs baseline: 11.9446x; 1.3931x over previous
#include <cuda_runtime.h>
#include <cuda_fp16.h>
#include <math.h>
#include <stdint.h>

#define B_SIZE 32768
#define E_DIM  256
#define NF     512
#define NWIN   6
#define BN_EPS 1e-5
#define KCAT   1792   // 512 (type0) + 512 (type1) + 768 (typeH)
#define NRV    50000

// ---------------- scratch (static device arrays) ----------------
__device__ float  g_out1[(size_t)2 * B_SIZE * NF];   // windows 0,1 (with bias)
__device__ float  g_H   [(size_t)B_SIZE * NF];       // H + b2
__device__ float  g_out2[(size_t)4 * B_SIZE * NF];   // windows 2..5 complete (H + p2)
__device__ float  g_sumf[NWIN * NF];
__device__ float  g_sqf [NWIN * NF];
__device__ float  g_scale[NWIN * NF];
__device__ float  g_shift[NWIN * NF];

// fp16 tables / weights
__device__ __half g_er[(size_t)NRV * E_DIM];
__device__ __half g_ev[(size_t)NRV * E_DIM];
__device__ __half g_w_h[(size_t)NF * KCAT];

// ---------------- helpers ----------------
__device__ __forceinline__ uint32_t smem_u32(const void* p) {
    uint32_t a;
    asm("{ .reg .u64 t; cvta.to.shared.u64 t, %1; cvt.u32.u64 %0, t; }" : "=r"(a) : "l"(p));
    return a;
}
__device__ __forceinline__ void cp16(uint32_t dst, const void* src) {
    asm volatile("cp.async.cg.shared.global [%0], [%1], 16;" :: "r"(dst), "l"(src));
}
__device__ __forceinline__ void ldsm4(uint32_t& r0, uint32_t& r1, uint32_t& r2, uint32_t& r3,
                                      uint32_t addr) {
    asm volatile("ldmatrix.sync.aligned.m8n8.x4.shared.b16 {%0,%1,%2,%3}, [%4];"
                 : "=r"(r0), "=r"(r1), "=r"(r2), "=r"(r3) : "r"(addr));
}
__device__ __forceinline__ void mma16816(float* d, const uint32_t* a, uint32_t b0, uint32_t b1) {
    asm volatile(
        "mma.sync.aligned.m16n8k16.row.col.f32.f16.f16.f32 "
        "{%0,%1,%2,%3}, {%4,%5,%6,%7}, {%8,%9}, {%0,%1,%2,%3};"
        : "+f"(d[0]), "+f"(d[1]), "+f"(d[2]), "+f"(d[3])
        : "r"(a[0]), "r"(a[1]), "r"(a[2]), "r"(a[3]), "r"(b0), "r"(b1));
}

// ---------------- prep kernels ----------------
__global__ void prep_tables_kernel(const float* __restrict__ er,
                                   const float* __restrict__ ev,
                                   int nre, int nve) {
    int total = nre + nve;
    for (int i = blockIdx.x * blockDim.x + threadIdx.x; i < total; i += gridDim.x * blockDim.x) {
        if (i < nre) g_er[i] = __float2half_rn(er[i]);
        else         g_ev[i - nre] = __float2half_rn(ev[i - nre]);
    }
}

__global__ void prep_w_kernel(const float* __restrict__ w1, const float* __restrict__ w2) {
    for (int i = blockIdx.x * blockDim.x + threadIdx.x; i < NF * KCAT; i += gridDim.x * blockDim.x) {
        int f = i / KCAT, k = i % KCAT;
        float v;
        if      (k < 256)  v = w1[((size_t)f * 2 + 0) * E_DIM + k];
        else if (k < 512)  v = w1[((size_t)f * 2 + 1) * E_DIM + (k - 256)];
        else if (k < 768)  v = w2[((size_t)f * 5 + 3) * E_DIM + (k - 512)];
        else if (k < 1024) v = w2[((size_t)f * 5 + 4) * E_DIM + (k - 768)];
        else if (k < 1280) v = w2[((size_t)f * 5 + 0) * E_DIM + (k - 1024)];
        else if (k < 1536) v = w2[((size_t)f * 5 + 1) * E_DIM + (k - 1280)];
        else               v = w2[((size_t)f * 5 + 2) * E_DIM + (k - 1536)];
        g_w_h[i] = __float2half_rn(v);
    }
}

__global__ void zero_stats_kernel() {
    int i = blockIdx.x * blockDim.x + threadIdx.x;
    if (i < NWIN * NF) { g_sumf[i] = 0.f; g_sqf[i] = 0.f; }
}

// ---------------- GEMM kernel (mma.sync fp16, single MMA) ----------------
// phase 0: typeH, grid (256, 4)  -> writes g_H (= H + b2)
// phase 1: type0/1, grid (1536, 4) -> writes g_out1 / g_out2(+H), computes BN stats
// block 256 (8 warps, 4x2; warp tile 32x64), 2 CTAs/SM.
// smem: [0,512) bias; [512,1536) stats red; stages at 4096, 2 x 32KB (A 16K | B 16K).
// Single barrier per chunk: wait(c) ; sync ; issue(c+1) ; mma(c).
#define SM_RED      512
#define SM_STAGE0   4096
#define STAGE_BYTES 32768
#define SMEM_TOTAL  (SM_STAGE0 + 2 * STAGE_BYTES)

__global__ __launch_bounds__(256, 2) void gemm_kernel(
    const int phase,
    const int* __restrict__ x,
    const float* __restrict__ bvec)
{
    extern __shared__ char smem[];
    const uint32_t sb = smem_u32(smem);
    const int tid = threadIdx.x, wid = tid >> 5, lane = tid & 31;
    const int f0 = blockIdx.y * 128;

    int type, sub, b0, nch, kbase;
    if (phase == 0) { type = 2; sub = 0; b0 = blockIdx.x * 128; nch = 12; kbase = 1024; }
    else {
        const int tile = blockIdx.x;
        if (tile < 512) { type = 0; sub = tile >> 8;         b0 = (tile & 255) * 128;         nch = 8; kbase = 0; }
        else            { type = 1; sub = (tile - 512) >> 8; b0 = ((tile - 512) & 255) * 128; nch = 8; kbase = 512; }
    }

    {
        const float* bp = (type == 1) ? (const float*)0 : bvec;
        float* sbias = (float*)smem;
        if (tid < 128) sbias[tid] = bp ? bp[f0 + tid] : 0.0f;
        float* sred = (float*)(smem + SM_RED);
        if (tid < 256) sred[tid] = 0.0f;
    }

    // ---- gather setup: hoist per-cq index loads ----
    const int row = tid >> 1, half2 = tid & 1;
    const __half* Ath[3];
    int aidx[3] = {0, 0, 0};
    {
        int cols[3] = {0, 0, 0};
        int ncq;
        if (type == 0)      { cols[0] = 2 * sub + 1; Ath[0] = g_ev;
                              cols[1] = 0;           Ath[1] = g_er; ncq = 2; Ath[2] = g_er; }
        else if (type == 1) { cols[0] = 4 + 2 * sub; Ath[0] = g_er;
                              cols[1] = 5 + 2 * sub; Ath[1] = g_ev; ncq = 2; Ath[2] = g_ev; }
        else                { cols[0] = 1; Ath[0] = g_ev;
                              cols[1] = 0; Ath[1] = g_er;
                              cols[2] = 3; Ath[2] = g_ev; ncq = 3; }
        const int* xrow = x + (size_t)(b0 + row) * 12;
#pragma unroll
        for (int q = 0; q < 3; q++)
            if (q < ncq) aidx[q] = __ldg(xrow + cols[q]);
    }

    auto issue_loads = [&](int cc) {
        const uint32_t tb = sb + SM_STAGE0 + (uint32_t)(cc & 1) * STAGE_BYTES;
        const uint32_t ro = (uint32_t)row * 128;
        const uint32_t xr = (uint32_t)(row & 7);
        // A row gather
        {
            const int cq = cc >> 2, e0 = (cc & 3) * 64;
            const char* sh = (const char*)(Ath[cq] + (size_t)aidx[cq] * E_DIM + e0);
#pragma unroll
            for (int g = 0; g < 4; g++) {
                const int gg = half2 * 4 + g;
                const uint32_t so = ro + (uint32_t)((gg ^ xr) * 16);
                cp16(tb + so, sh + gg * 16);
            }
        }
        // B rows (feature f0+row)
        {
            const char* ph = (const char*)(g_w_h + (size_t)(f0 + row) * KCAT + kbase + cc * 64);
#pragma unroll
            for (int g = 0; g < 4; g++) {
                const int gg = half2 * 4 + g;
                const uint32_t so = ro + (uint32_t)((gg ^ xr) * 16);
                cp16(tb + 16384 + so, ph + gg * 16);
            }
        }
        asm volatile("cp.async.commit_group;" ::: "memory");
    };

    // ---- per-warp frag addressing ----
    const int warpM = (wid & 3) * 32;
    const int warpN = (wid >> 2) * 64;
    uint32_t aOff[2], aXor[2];
#pragma unroll
    for (int mi = 0; mi < 2; mi++) {
        const int r = warpM + mi * 16 + (lane & 15);
        aOff[mi] = (uint32_t)r * 128;
        aXor[mi] = (uint32_t)(r & 7);
    }
    const uint32_t aSel = (uint32_t)((lane >> 4) & 1);
    uint32_t bOff[4], bXor[4];
#pragma unroll
    for (int p = 0; p < 4; p++) {
        const int r = warpN + p * 16 + (lane & 7) + (((lane >> 4) & 1) << 3);
        bOff[p] = (uint32_t)r * 128;
        bXor[p] = (uint32_t)(r & 7);
    }
    const uint32_t bSel = (uint32_t)((lane >> 3) & 1);

    float acc[2][8][4];
#pragma unroll
    for (int mi = 0; mi < 2; mi++)
#pragma unroll
        for (int ni = 0; ni < 8; ni++)
#pragma unroll
            for (int q = 0; q < 4; q++) acc[mi][ni][q] = 0.f;

    issue_loads(0);

    for (int c = 0; c < nch; c++) {
        asm volatile("cp.async.wait_group 0;" ::: "memory");
        __syncthreads();                 // chunk c data ready; all warps done with c-1
        if (c + 1 < nch) issue_loads(c + 1);   // other buffer (last read in c-1) — safe

        const uint32_t tb = sb + SM_STAGE0 + (uint32_t)(c & 1) * STAGE_BYTES;
#pragma unroll
        for (int s = 0; s < 4; s++) {
            uint32_t fah[2][4], fb[4][4];
            const uint32_t blk = (uint32_t)(2 * s);
#pragma unroll
            for (int mi = 0; mi < 2; mi++) {
                const uint32_t ad = tb + aOff[mi] + (((blk + aSel) ^ aXor[mi]) * 16);
                ldsm4(fah[mi][0], fah[mi][1], fah[mi][2], fah[mi][3], ad);
            }
#pragma unroll
            for (int p = 0; p < 4; p++) {
                const uint32_t bd = tb + 16384 + bOff[p] + (((blk + bSel) ^ bXor[p]) * 16);
                ldsm4(fb[p][0], fb[p][1], fb[p][2], fb[p][3], bd);
            }
#pragma unroll
            for (int mi = 0; mi < 2; mi++)
#pragma unroll
                for (int ni = 0; ni < 8; ni++) {
                    const int p = ni >> 1, o = (ni & 1) * 2;
                    mma16816(acc[mi][ni], fah[mi], fb[p][o], fb[p][o + 1]);
                }
        }
    }

    // ---- epilogue ----
    const float* sbias = (const float*)smem;
    float* sred = (float*)(smem + SM_RED);
    const int lr = lane >> 2, lc = (lane & 3) * 2;
    const int nhalf = wid >> 2;

    if (type == 2) {
#pragma unroll
        for (int mi = 0; mi < 2; mi++) {
            const size_t r0 = (size_t)b0 + warpM + mi * 16 + lr;
#pragma unroll
            for (int ni = 0; ni < 8; ni++) {
                const int colLocal = warpN + ni * 8 + lc;
                const int f = f0 + colLocal;
                const float bi0 = sbias[colLocal], bi1 = sbias[colLocal + 1];
                float2 v0 = {acc[mi][ni][0] + bi0, acc[mi][ni][1] + bi1};
                float2 v1 = {acc[mi][ni][2] + bi0, acc[mi][ni][3] + bi1};
                *(float2*)(g_H + r0 * NF + f)       = v0;
                *(float2*)(g_H + (r0 + 8) * NF + f) = v1;
            }
        }
        return;
    }

    const int w = (type == 0) ? sub : (2 + sub);
    float* plane = (type == 0) ? g_out1 : g_out2;
    const size_t rowbase = (size_t)sub * B_SIZE + b0;

#pragma unroll
    for (int ni = 0; ni < 8; ni++) {
        const int colLocal = warpN + ni * 8 + lc;
        const int f = f0 + colLocal;
        const float bi0 = sbias[colLocal], bi1 = sbias[colLocal + 1];
        float s0 = 0.f, q0 = 0.f, s1 = 0.f, q1 = 0.f;
#pragma unroll
        for (int mi = 0; mi < 2; mi++) {
            const size_t hr0 = (size_t)b0 + warpM + mi * 16 + lr;
            float v00 = acc[mi][ni][0] + bi0;
            float v01 = acc[mi][ni][1] + bi1;
            float v10 = acc[mi][ni][2] + bi0;
            float v11 = acc[mi][ni][3] + bi1;
            if (type == 1) {
                float2 h0 = *(const float2*)(g_H + hr0 * NF + f);
                float2 h1 = *(const float2*)(g_H + (hr0 + 8) * NF + f);
                v00 += h0.x; v01 += h0.y; v10 += h1.x; v11 += h1.y;
            }
            const size_t r0 = rowbase + warpM + mi * 16 + lr;
            *(float2*)(plane + r0 * NF + f)       = make_float2(v00, v01);
            *(float2*)(plane + (r0 + 8) * NF + f) = make_float2(v10, v11);
            s0 += v00 + v10; q0 += v00 * v00 + v10 * v10;
            s1 += v01 + v11; q1 += v01 * v01 + v11 * v11;
        }
#pragma unroll
        for (int off = 4; off < 32; off <<= 1) {
            s0 += __shfl_xor_sync(0xFFFFFFFFu, s0, off);
            q0 += __shfl_xor_sync(0xFFFFFFFFu, q0, off);
            s1 += __shfl_xor_sync(0xFFFFFFFFu, s1, off);
            q1 += __shfl_xor_sync(0xFFFFFFFFu, q1, off);
        }
        if (lane < 4) {
            const int cl = nhalf * 64 + ni * 8 + lane * 2;
            atomicAdd(&sred[cl], s0);       atomicAdd(&sred[128 + cl], q0);
            atomicAdd(&sred[cl + 1], s1);   atomicAdd(&sred[128 + cl + 1], q1);
        }
    }
    __syncthreads();
    if (tid < 128)      atomicAdd(&g_sumf[w * NF + f0 + tid], sred[tid]);
    else if (tid < 256) atomicAdd(&g_sqf [w * NF + f0 + (tid - 128)], sred[tid]);
}

// ---------------- finalize scale/shift ----------------
__global__ void bn_finalize_kernel(
    const float* __restrict__ g1, const float* __restrict__ be1,
    const float* __restrict__ g2, const float* __restrict__ be2)
{
    int c = blockIdx.x * blockDim.x + threadIdx.x;
    if (c >= NWIN * NF) return;
    int w = c >> 9;
    int f = c & (NF - 1);
    double mean = (double)g_sumf[c] / (double)B_SIZE;
    double var  = (double)g_sqf[c] / (double)B_SIZE - mean * mean;
    float gamma = (w < 2) ? g1[f] : g2[f];
    float beta  = (w < 2) ? be1[f] : be2[f];
    double istd = rsqrt(var + BN_EPS);
    float sc = (float)(gamma * istd);
    g_scale[c] = sc;
    g_shift[c] = beta - (float)(mean * (double)sc);
}

// ---------------- BN + relu + min + fc ----------------
__global__ __launch_bounds__(128) void final_kernel(
    const float* __restrict__ fc_w,
    const float* __restrict__ fc_b,
    float* __restrict__ out)
{
    const int b   = blockIdx.x;
    const int tid = threadIdx.x;
    const int f   = tid * 4;

    float4 o0 = *(const float4*)&g_out1[(size_t)b * NF + f];
    float4 o1 = *(const float4*)&g_out1[((size_t)B_SIZE + b) * NF + f];
    float4 p[4];
#pragma unroll
    for (int k = 0; k < 4; k++)
        p[k] = *(const float4*)&g_out2[((size_t)k * B_SIZE + b) * NF + f];

    float acc = 0.f;
#pragma unroll
    for (int l = 0; l < 4; l++) {
        const int fl = f + l;
        float x0 = (l == 0 ? o0.x : l == 1 ? o0.y : l == 2 ? o0.z : o0.w);
        float x1 = (l == 0 ? o1.x : l == 1 ? o1.y : l == 2 ? o1.z : o1.w);
        float m = fmaxf(0.f, x0 * g_scale[0 * NF + fl] + g_shift[0 * NF + fl]);
        m = fminf(m, fmaxf(0.f, x1 * g_scale[1 * NF + fl] + g_shift[1 * NF + fl]));
#pragma unroll
        for (int k = 0; k < 4; k++) {
            float pk = (l == 0 ? p[k].x : l == 1 ? p[k].y : l == 2 ? p[k].z : p[k].w);
            m = fminf(m, fmaxf(0.f, pk * g_scale[(2 + k) * NF + fl] + g_shift[(2 + k) * NF + fl]));
        }
        acc += fc_w[fl] * m;
    }

    __shared__ float red[4];
#pragma unroll
    for (int o = 16; o > 0; o >>= 1) acc += __shfl_down_sync(0xFFFFFFFFu, acc, o);
    if ((tid & 31) == 0) red[tid >> 5] = acc;
    __syncthreads();
    if (tid == 0) out[b] = red[0] + red[1] + red[2] + red[3] + fc_b[0];
}

// ---------------- launch ----------------
extern "C" void kernel_launch(void* const* d_in, const int* in_sizes, int n_in,
                              void* d_out, int out_size) {
    int o = (in_sizes[1] == 1) ? 1 : 0;  // skip scalar arity if present
    const int*   x      = (const int*)  d_in[0];
    const float* emb_r  = (const float*)d_in[1 + o];
    const float* emb_v  = (const float*)d_in[2 + o];
    const float* w1     = (const float*)d_in[3 + o];
    const float* b1     = (const float*)d_in[4 + o];
    const float* bn1_g  = (const float*)d_in[5 + o];
    const float* bn1_b  = (const float*)d_in[6 + o];
    const float* w2     = (const float*)d_in[7 + o];
    const float* b2     = (const float*)d_in[8 + o];
    const float* bn2_g  = (const float*)d_in[9 + o];
    const float* bn2_b  = (const float*)d_in[10 + o];
    const float* fc_w   = (const float*)d_in[11 + o];
    const float* fc_b   = (const float*)d_in[12 + o];
    float* out = (float*)d_out;

    cudaFuncSetAttribute(gemm_kernel, cudaFuncAttributeMaxDynamicSharedMemorySize, SMEM_TOTAL);

    const int nre = in_sizes[1 + o];  // NR*E
    const int nve = in_sizes[2 + o];  // NV*E

    prep_tables_kernel<<<2048, 256>>>(emb_r, emb_v, nre, nve);
    prep_w_kernel<<<1024, 256>>>(w1, w2);
    zero_stats_kernel<<<(NWIN * NF + 255) / 256, 256>>>();

    // phase 0: typeH -> g_H
    gemm_kernel<<<dim3(256, 4), 256, SMEM_TOTAL>>>(0, x, b2);
    // phase 1: type0/1 -> planes + stats (reads g_H)
    gemm_kernel<<<dim3(1536, 4), 256, SMEM_TOTAL>>>(1, x, b1);

    bn_finalize_kernel<<<(NWIN * NF + 255) / 256, 256>>>(bn1_g, bn1_b, bn2_g, bn2_b);
    final_kernel<<<B_SIZE, 128>>>(fc_w, fc_b, out);
}